// round 1
// baseline (speedup 1.0000x reference)
#include <cuda_runtime.h>
#include <math.h>
#include <stdint.h>

// Problem constants
#define BB   2
#define LL   2048
#define DD   1024
#define FF   4096
#define NH   16
#define DK   64
#define BL   (BB*LL)        // 4096 rows total

// ---------------------------------------------------------------------------
// Scratch (device global; no allocations allowed)
// layout: q | k | v | ctx | attn | h | ff2   (each BL*DD)   then ff1 (BL*FF)
// ---------------------------------------------------------------------------
__device__ float g_scratch[(size_t)7 * BL * DD + (size_t)BL * FF];

// ---------------------------------------------------------------------------
// SGEMM: C[M,N] = A[M,K] @ B[K,N] (+bias) (+relu)
// 128x128 tile, k-step 8, 256 threads, 8x8 per-thread microtile
// Requires M%128==0, N%128==0, K%8==0 (true for all shapes here)
// ---------------------------------------------------------------------------
template<bool BIAS, bool RELU>
__global__ void sgemm128(const float* __restrict__ A, const float* __restrict__ Bm,
                         const float* __restrict__ bias, float* __restrict__ C,
                         int M, int N, int K) {
    __shared__ __align__(16) float As[8][128];
    __shared__ __align__(16) float Bs[8][128];

    const int bx = blockIdx.x;        // N tile
    const int by = blockIdx.y;        // M tile
    const int tid = threadIdx.x;
    const int tx = tid & 15;          // col group (0..15)
    const int ty = tid >> 4;          // row group (0..15)

    const int aRow  = tid >> 1;       // 0..127
    const int aCol4 = (tid & 1) * 4;  // 0 or 4
    const int bRow  = tid >> 5;       // 0..7
    const int bCol4 = (tid & 31) * 4; // 0..124

    const float* Aptr = A + (size_t)(by * 128 + aRow) * K + aCol4;
    const float* Bptr = Bm + (size_t)bRow * N + bx * 128 + bCol4;

    float acc[8][8];
#pragma unroll
    for (int i = 0; i < 8; i++)
#pragma unroll
        for (int j = 0; j < 8; j++) acc[i][j] = 0.f;

    // prologue load
    float4 a4 = *(const float4*)(Aptr);
    float4 b4 = *(const float4*)(Bptr);

    for (int k0 = 0; k0 < K; k0 += 8) {
        // store current tile to smem
        As[aCol4 + 0][aRow] = a4.x;
        As[aCol4 + 1][aRow] = a4.y;
        As[aCol4 + 2][aRow] = a4.z;
        As[aCol4 + 3][aRow] = a4.w;
        *(float4*)&Bs[bRow][bCol4] = b4;
        __syncthreads();

        // prefetch next tile into registers (overlaps with compute)
        if (k0 + 8 < K) {
            a4 = *(const float4*)(Aptr + (k0 + 8));
            b4 = *(const float4*)(Bptr + (size_t)(k0 + 8) * N);
        }

#pragma unroll
        for (int kk = 0; kk < 8; kk++) {
            float4 av0 = *(const float4*)&As[kk][ty * 8];
            float4 av1 = *(const float4*)&As[kk][ty * 8 + 4];
            float4 bv0 = *(const float4*)&Bs[kk][tx * 8];
            float4 bv1 = *(const float4*)&Bs[kk][tx * 8 + 4];
            float ar[8] = {av0.x, av0.y, av0.z, av0.w, av1.x, av1.y, av1.z, av1.w};
            float br[8] = {bv0.x, bv0.y, bv0.z, bv0.w, bv1.x, bv1.y, bv1.z, bv1.w};
#pragma unroll
            for (int i = 0; i < 8; i++)
#pragma unroll
                for (int j = 0; j < 8; j++)
                    acc[i][j] = fmaf(ar[i], br[j], acc[i][j]);
        }
        __syncthreads();
    }

    const int cRow0 = by * 128 + ty * 8;
    const int cCol0 = bx * 128 + tx * 8;
#pragma unroll
    for (int i = 0; i < 8; i++) {
        float* crow = C + (size_t)(cRow0 + i) * N + cCol0;
#pragma unroll
        for (int j = 0; j < 8; j++) {
            float v = acc[i][j];
            if (BIAS) v += bias[cCol0 + j];
            if (RELU) v = fmaxf(v, 0.f);
            crow[j] = v;
        }
    }
}

// ---------------------------------------------------------------------------
// RoPE applied in-place on [BL, D] tensor laid out as (b,l,h,d)
// one thread per (row, head, i) with i in [0,32)
// ---------------------------------------------------------------------------
__global__ void rope_kernel(float* __restrict__ t) {
    int idx = blockIdx.x * blockDim.x + threadIdx.x;
    if (idx >= BL * NH * 32) return;
    int i = idx & 31;
    int h = (idx >> 5) & (NH - 1);
    int row = idx >> 9;
    int l = row & (LL - 1);

    float inv = powf(10000.f, -(float)(2 * i) / (float)DK);
    float fr = (float)l * inv;
    float s, c;
    sincosf(fr, &s, &c);

    float* base = t + (size_t)row * DD + h * DK;
    float x1 = base[i];
    float x2 = base[i + 32];
    base[i]      = x1 * c - x2 * s;
    base[i + 32] = x1 * s + x2 * c;
}

// ---------------------------------------------------------------------------
// Flash attention (fp32, online softmax)
// grid: (L/64, B*NH), 256 threads
// Q,K,V,O layout: [row = b*L + l][ D ], head h at columns h*64..h*64+63
// ---------------------------------------------------------------------------
#define SPAD 65
__global__ void flash_attn_kernel(const float* __restrict__ Q, const float* __restrict__ K,
                                  const float* __restrict__ V, float* __restrict__ O) {
    extern __shared__ float sm[];
    float* Qs = sm;                   // 64*65
    float* Ks = Qs + 64 * SPAD;       // 64*65
    float* Vs = Ks + 64 * SPAD;       // 64*65
    float* Ss = Vs + 64 * SPAD;       // 64*65
    float* mrow = Ss + 64 * SPAD;     // 64
    float* lrow = mrow + 64;          // 64
    float* frow = lrow + 64;          // 64

    const int qt = blockIdx.x;            // q tile index
    const int bh = blockIdx.y;            // b*NH + h
    const int b = bh / NH;
    const int h = bh % NH;
    const size_t base = ((size_t)b * LL) * DD + (size_t)h * DK;

    const int tid = threadIdx.x;
    const int lane = tid & 31;
    const int wid = tid >> 5;

    // load Q tile, pre-scaled by 1/sqrt(dk)
    for (int idx = tid; idx < 64 * 64; idx += 256) {
        int r = idx >> 6, c = idx & 63;
        Qs[r * SPAD + c] = Q[base + (size_t)(qt * 64 + r) * DD + c] * 0.125f;
    }
    if (tid < 64) { mrow[tid] = -INFINITY; lrow[tid] = 0.f; }

    // per-thread output accumulator: rows r0..r0+3 (q), cols c0..c0+3 (d)
    const int r0 = (tid >> 4) * 4;
    const int c0 = (tid & 15) * 4;
    float oacc[4][4];
#pragma unroll
    for (int i = 0; i < 4; i++)
#pragma unroll
        for (int j = 0; j < 4; j++) oacc[i][j] = 0.f;

    __syncthreads();

    for (int kt = 0; kt < LL / 64; kt++) {
        // load K,V tiles
        for (int idx = tid; idx < 64 * 64; idx += 256) {
            int r = idx >> 6, c = idx & 63;
            size_t g = base + (size_t)(kt * 64 + r) * DD + c;
            Ks[r * SPAD + c] = K[g];
            Vs[r * SPAD + c] = V[g];
        }
        __syncthreads();

        // S = Qs @ Ks^T  (64x64), each thread computes 4x4
        float sacc[4][4];
#pragma unroll
        for (int i = 0; i < 4; i++)
#pragma unroll
            for (int j = 0; j < 4; j++) sacc[i][j] = 0.f;

#pragma unroll 4
        for (int kk = 0; kk < 64; kk++) {
            float a0 = Qs[(r0 + 0) * SPAD + kk];
            float a1 = Qs[(r0 + 1) * SPAD + kk];
            float a2 = Qs[(r0 + 2) * SPAD + kk];
            float a3 = Qs[(r0 + 3) * SPAD + kk];
            float b0 = Ks[(c0 + 0) * SPAD + kk];
            float b1 = Ks[(c0 + 1) * SPAD + kk];
            float b2 = Ks[(c0 + 2) * SPAD + kk];
            float b3 = Ks[(c0 + 3) * SPAD + kk];
            sacc[0][0] = fmaf(a0, b0, sacc[0][0]); sacc[0][1] = fmaf(a0, b1, sacc[0][1]);
            sacc[0][2] = fmaf(a0, b2, sacc[0][2]); sacc[0][3] = fmaf(a0, b3, sacc[0][3]);
            sacc[1][0] = fmaf(a1, b0, sacc[1][0]); sacc[1][1] = fmaf(a1, b1, sacc[1][1]);
            sacc[1][2] = fmaf(a1, b2, sacc[1][2]); sacc[1][3] = fmaf(a1, b3, sacc[1][3]);
            sacc[2][0] = fmaf(a2, b0, sacc[2][0]); sacc[2][1] = fmaf(a2, b1, sacc[2][1]);
            sacc[2][2] = fmaf(a2, b2, sacc[2][2]); sacc[2][3] = fmaf(a2, b3, sacc[2][3]);
            sacc[3][0] = fmaf(a3, b0, sacc[3][0]); sacc[3][1] = fmaf(a3, b1, sacc[3][1]);
            sacc[3][2] = fmaf(a3, b2, sacc[3][2]); sacc[3][3] = fmaf(a3, b3, sacc[3][3]);
        }
#pragma unroll
        for (int i = 0; i < 4; i++)
#pragma unroll
            for (int j = 0; j < 4; j++)
                Ss[(r0 + i) * SPAD + (c0 + j)] = sacc[i][j];
        __syncthreads();

        // online softmax per row: warp wid handles rows wid*8..wid*8+7
        for (int rr = 0; rr < 8; rr++) {
            int row = wid * 8 + rr;
            float s0 = Ss[row * SPAD + lane];
            float s1 = Ss[row * SPAD + lane + 32];
            float mx = fmaxf(s0, s1);
#pragma unroll
            for (int off = 16; off; off >>= 1)
                mx = fmaxf(mx, __shfl_xor_sync(0xffffffffu, mx, off));
            float mold = mrow[row];
            float mnew = fmaxf(mold, mx);
            float p0 = __expf(s0 - mnew);
            float p1 = __expf(s1 - mnew);
            Ss[row * SPAD + lane] = p0;
            Ss[row * SPAD + lane + 32] = p1;
            float psum = p0 + p1;
#pragma unroll
            for (int off = 16; off; off >>= 1)
                psum += __shfl_xor_sync(0xffffffffu, psum, off);
            if (lane == 0) {
                float fac = __expf(mold - mnew);
                frow[row] = fac;
                lrow[row] = lrow[row] * fac + psum;
                mrow[row] = mnew;
            }
        }
        __syncthreads();

        // rescale output accumulator and accumulate P @ V
        float f0 = frow[r0 + 0], f1 = frow[r0 + 1], f2 = frow[r0 + 2], f3 = frow[r0 + 3];
#pragma unroll
        for (int j = 0; j < 4; j++) {
            oacc[0][j] *= f0; oacc[1][j] *= f1; oacc[2][j] *= f2; oacc[3][j] *= f3;
        }
#pragma unroll 4
        for (int kk = 0; kk < 64; kk++) {
            float p0 = Ss[(r0 + 0) * SPAD + kk];
            float p1 = Ss[(r0 + 1) * SPAD + kk];
            float p2 = Ss[(r0 + 2) * SPAD + kk];
            float p3 = Ss[(r0 + 3) * SPAD + kk];
            float v0 = Vs[kk * SPAD + c0 + 0];
            float v1 = Vs[kk * SPAD + c0 + 1];
            float v2 = Vs[kk * SPAD + c0 + 2];
            float v3 = Vs[kk * SPAD + c0 + 3];
            oacc[0][0] = fmaf(p0, v0, oacc[0][0]); oacc[0][1] = fmaf(p0, v1, oacc[0][1]);
            oacc[0][2] = fmaf(p0, v2, oacc[0][2]); oacc[0][3] = fmaf(p0, v3, oacc[0][3]);
            oacc[1][0] = fmaf(p1, v0, oacc[1][0]); oacc[1][1] = fmaf(p1, v1, oacc[1][1]);
            oacc[1][2] = fmaf(p1, v2, oacc[1][2]); oacc[1][3] = fmaf(p1, v3, oacc[1][3]);
            oacc[2][0] = fmaf(p2, v0, oacc[2][0]); oacc[2][1] = fmaf(p2, v1, oacc[2][1]);
            oacc[2][2] = fmaf(p2, v2, oacc[2][2]); oacc[2][3] = fmaf(p2, v3, oacc[2][3]);
            oacc[3][0] = fmaf(p3, v0, oacc[3][0]); oacc[3][1] = fmaf(p3, v1, oacc[3][1]);
            oacc[3][2] = fmaf(p3, v2, oacc[3][2]); oacc[3][3] = fmaf(p3, v3, oacc[3][3]);
        }
        __syncthreads();
    }

    // finalize: divide by softmax denominator, write out
#pragma unroll
    for (int i = 0; i < 4; i++) {
        float inv_l = 1.f / lrow[r0 + i];
        float* orow = O + base + (size_t)(qt * 64 + r0 + i) * DD + c0;
#pragma unroll
        for (int j = 0; j < 4; j++) orow[j] = oacc[i][j] * inv_l;
    }
}

// ---------------------------------------------------------------------------
// out = LayerNorm(a + b) with gamma/beta; one block (256 thr) per row, D=1024
// ---------------------------------------------------------------------------
__global__ void add_ln_kernel(const float* __restrict__ a, const float* __restrict__ b,
                              const float* __restrict__ gamma, const float* __restrict__ beta,
                              float* __restrict__ o) {
    const int row = blockIdx.x;
    const int tid = threadIdx.x;
    const float* pa = a + (size_t)row * DD;
    const float* pb = b + (size_t)row * DD;

    float v[4];
    float s = 0.f;
#pragma unroll
    for (int i = 0; i < 4; i++) {
        int c = tid + i * 256;
        v[i] = pa[c] + pb[c];
        s += v[i];
    }

    __shared__ float red[8];
    __shared__ float smean, srstd;
#pragma unroll
    for (int off = 16; off; off >>= 1) s += __shfl_xor_sync(0xffffffffu, s, off);
    if ((tid & 31) == 0) red[tid >> 5] = s;
    __syncthreads();
    if (tid == 0) {
        float t = 0.f;
#pragma unroll
        for (int i = 0; i < 8; i++) t += red[i];
        smean = t * (1.f / (float)DD);
    }
    __syncthreads();
    float mean = smean;

    float s2 = 0.f;
#pragma unroll
    for (int i = 0; i < 4; i++) {
        float d = v[i] - mean;
        s2 += d * d;
    }
#pragma unroll
    for (int off = 16; off; off >>= 1) s2 += __shfl_xor_sync(0xffffffffu, s2, off);
    if ((tid & 31) == 0) red[tid >> 5] = s2;
    __syncthreads();
    if (tid == 0) {
        float t = 0.f;
#pragma unroll
        for (int i = 0; i < 8; i++) t += red[i];
        srstd = rsqrtf(t * (1.f / (float)DD) + 1e-6f);
    }
    __syncthreads();
    float rstd = srstd;

    float* po = o + (size_t)row * DD;
#pragma unroll
    for (int i = 0; i < 4; i++) {
        int c = tid + i * 256;
        po[c] = gamma[c] * (v[i] - mean) * rstd + beta[c];
    }
}

// ---------------------------------------------------------------------------
// Launch
// ---------------------------------------------------------------------------
extern "C" void kernel_launch(void* const* d_in, const int* in_sizes, int n_in,
                              void* d_out, int out_size) {
    const float* x      = (const float*)d_in[0];
    const float* w_q    = (const float*)d_in[1];
    const float* w_k    = (const float*)d_in[2];
    const float* w_v    = (const float*)d_in[3];
    const float* w_o    = (const float*)d_in[4];
    const float* b_o    = (const float*)d_in[5];
    const float* gamma1 = (const float*)d_in[6];
    const float* beta1  = (const float*)d_in[7];
    const float* gamma2 = (const float*)d_in[8];
    const float* beta2  = (const float*)d_in[9];
    const float* w1     = (const float*)d_in[10];
    const float* b1     = (const float*)d_in[11];
    const float* w2     = (const float*)d_in[12];
    const float* b2     = (const float*)d_in[13];
    float* out = (float*)d_out;

    float* scratch = nullptr;
    cudaGetSymbolAddress((void**)&scratch, g_scratch);
    float* q    = scratch + (size_t)0 * BL * DD;
    float* k    = scratch + (size_t)1 * BL * DD;
    float* v    = scratch + (size_t)2 * BL * DD;
    float* ctx  = scratch + (size_t)3 * BL * DD;
    float* attn = scratch + (size_t)4 * BL * DD;
    float* hbuf = scratch + (size_t)5 * BL * DD;
    float* ff2  = scratch + (size_t)6 * BL * DD;
    float* ff1  = scratch + (size_t)7 * BL * DD;

    const int flash_smem = (4 * 64 * SPAD + 3 * 64) * (int)sizeof(float); // ~67 KB
    cudaFuncSetAttribute(flash_attn_kernel, cudaFuncAttributeMaxDynamicSharedMemorySize, flash_smem);

    dim3 blk(256);

    // QKV projections: [4096,1024] = [4096,1024] @ [1024,1024]
    dim3 gproj(DD / 128, BL / 128);
    sgemm128<false, false><<<gproj, blk>>>(x, w_q, nullptr, q, BL, DD, DD);
    sgemm128<false, false><<<gproj, blk>>>(x, w_k, nullptr, k, BL, DD, DD);
    sgemm128<false, false><<<gproj, blk>>>(x, w_v, nullptr, v, BL, DD, DD);

    // RoPE on q and k
    int rope_total = BL * NH * 32;
    rope_kernel<<<(rope_total + 255) / 256, blk>>>(q);
    rope_kernel<<<(rope_total + 255) / 256, blk>>>(k);

    // Flash attention -> ctx
    dim3 gattn(LL / 64, BB * NH);
    flash_attn_kernel<<<gattn, blk, flash_smem>>>(q, k, v, ctx);

    // attn_out = ctx @ w_o + b_o
    sgemm128<true, false><<<gproj, blk>>>(ctx, w_o, b_o, attn, BL, DD, DD);

    // h = LN(x + attn_out)
    add_ln_kernel<<<BL, blk>>>(x, attn, gamma1, beta1, hbuf);

    // ff1 = relu(h @ w1 + b1): [4096,4096]
    dim3 gff1(FF / 128, BL / 128);
    sgemm128<true, true><<<gff1, blk>>>(hbuf, w1, b1, ff1, BL, FF, DD);

    // ff2 = ff1 @ w2 + b2: [4096,1024]
    dim3 gff2(DD / 128, BL / 128);
    sgemm128<true, false><<<gff2, blk>>>(ff1, w2, b2, ff2, BL, DD, FF);

    // out = LN(h + ff2)
    add_ln_kernel<<<BL, blk>>>(hbuf, ff2, gamma2, beta2, out);
}

// round 2
// speedup vs baseline: 5.5007x; 5.5007x over previous
#include <cuda_runtime.h>
#include <cuda_fp16.h>
#include <math.h>
#include <stdint.h>

#define BB 2
#define LL 2048
#define DD 1024
#define FF 4096
#define NH 16
#define DK 64
#define BL (BB*LL)

// ---------------------------------------------------------------------------
// Scratch (device globals; no allocations allowed)
// ---------------------------------------------------------------------------
// halves: xh | q | k | v | ctx | hh (each BL*DD) | ff1 (BL*FF) | wq wk wv wo (DD*DD) | w1 w2 (DD*FF)
__device__ __half g_h[(size_t)6*BL*DD + (size_t)BL*FF + (size_t)4*DD*DD + (size_t)2*DD*FF];
// floats: attn | hbuf | ff2 (each BL*DD)
__device__ float  g_f[(size_t)3*BL*DD];

// ---------------------------------------------------------------------------
// PTX helpers
// ---------------------------------------------------------------------------
__device__ __forceinline__ uint32_t smem_u32(const void* p){
    return (uint32_t)__cvta_generic_to_shared(p);
}
__device__ __forceinline__ void cp16(uint32_t s, const void* g){
    asm volatile("cp.async.cg.shared.global [%0], [%1], 16;\n" :: "r"(s), "l"(g));
}
__device__ __forceinline__ void cp_commit(){ asm volatile("cp.async.commit_group;\n"); }
template<int N> __device__ __forceinline__ void cp_wait(){
    asm volatile("cp.async.wait_group %0;\n" :: "n"(N));
}
__device__ __forceinline__ void ldm_x4(uint32_t* r, uint32_t addr){
    asm volatile("ldmatrix.sync.aligned.m8n8.x4.shared.b16 {%0,%1,%2,%3}, [%4];\n"
        : "=r"(r[0]),"=r"(r[1]),"=r"(r[2]),"=r"(r[3]) : "r"(addr));
}
__device__ __forceinline__ void ldm_x4t(uint32_t* r, uint32_t addr){
    asm volatile("ldmatrix.sync.aligned.m8n8.x4.trans.shared.b16 {%0,%1,%2,%3}, [%4];\n"
        : "=r"(r[0]),"=r"(r[1]),"=r"(r[2]),"=r"(r[3]) : "r"(addr));
}
__device__ __forceinline__ void mma16816(float* d, const uint32_t* a, const uint32_t* b){
    asm volatile("mma.sync.aligned.m16n8k16.row.col.f32.f16.f16.f32 "
        "{%0,%1,%2,%3}, {%4,%5,%6,%7}, {%8,%9}, {%0,%1,%2,%3};\n"
        : "+f"(d[0]),"+f"(d[1]),"+f"(d[2]),"+f"(d[3])
        : "r"(a[0]),"r"(a[1]),"r"(a[2]),"r"(a[3]), "r"(b[0]),"r"(b[1]));
}
__device__ __forceinline__ uint32_t packh2(float x, float y){
    __half2 h = __floats2half2_rn(x, y);
    return *reinterpret_cast<uint32_t*>(&h);
}

// ---------------------------------------------------------------------------
// fp32 -> fp16 conversion (vectorized by 4)
// ---------------------------------------------------------------------------
__global__ void f2h(const float* __restrict__ s, __half* __restrict__ d, int n){
    int i = (blockIdx.x*blockDim.x + threadIdx.x)*4;
    if (i >= n) return;
    float4 f = *(const float4*)(s+i);
    __half2 lo = __floats2half2_rn(f.x, f.y);
    __half2 hi = __floats2half2_rn(f.z, f.w);
    uint2 u; u.x = *reinterpret_cast<uint32_t*>(&lo); u.y = *reinterpret_cast<uint32_t*>(&hi);
    *(uint2*)(d+i) = u;
}

// ---------------------------------------------------------------------------
// fp16 GEMM: C[M,N] = A[M,K] @ B[K,N] (+bias)(+relu), fp32 accum
// 128x128x32 block tile, 256 thr (8 warps 2x4), warp 64x32, mma m16n8k16
// ---------------------------------------------------------------------------
#define AP 40    // As row stride (halves), padded for ldmatrix bank spread
#define BP 136   // Bs row stride (halves)

template<typename OutT, bool BIAS, bool RELU>
__global__ void __launch_bounds__(256,1) hgemm(const __half* __restrict__ A,
    const __half* __restrict__ Bm, const float* __restrict__ bias,
    OutT* __restrict__ C, int M, int N, int K)
{
    __shared__ __half As[2][128*AP];
    __shared__ __half Bs[2][32*BP];

    const int tid = threadIdx.x;
    const int warp = tid>>5, lane = tid&31;
    const int wm = warp>>2, wn = warp&3;
    const int gr = lane>>2, tig = lane&3;

    // cp.async mapping: 32B contiguous per thread
    const int arow = tid>>1,  acol = (tid&1)*16;   // A: 128 rows x 32 halves
    const int brow = tid>>3,  bcol = (tid&7)*16;   // B: 32 rows x 128 halves

    const __half* Ag = A + (size_t)(blockIdx.y*128 + arow)*K + acol;
    const __half* Bg = Bm + (size_t)brow*N + blockIdx.x*128 + bcol;

    uint32_t sA[2], sB[2];
    sA[0] = smem_u32(&As[0][arow*AP + acol]); sA[1] = smem_u32(&As[1][arow*AP + acol]);
    sB[0] = smem_u32(&Bs[0][brow*BP + bcol]); sB[1] = smem_u32(&Bs[1][brow*BP + bcol]);

    // ldmatrix lane geometry
    const int a_r = wm*64 + (lane&15);            // A frag row
    const int a_c = (lane>>4)*8;                  // A frag col offset
    const int b_k = (lane&7) + ((lane>>3)&1)*8;   // B frag k-row offset
    const int b_n = wn*32 + ((lane>>4)&1)*8;      // B frag n-col offset

    float acc[4][4][4];
#pragma unroll
    for (int i=0;i<4;i++)
#pragma unroll
        for (int j=0;j<4;j++)
#pragma unroll
            for (int t=0;t<4;t++) acc[i][j][t] = 0.f;

    const int KT = K/32;
    // prologue: tile 0
    cp16(sA[0], Ag); cp16(sA[0]+16, Ag+8);
    cp16(sB[0], Bg); cp16(sB[0]+16, Bg+8);
    cp_commit();

    for (int kt=0; kt<KT; ++kt){
        const int buf = kt&1;
        if (kt+1 < KT){
            const int nb = buf^1;
            const __half* ag = Ag + (kt+1)*32;
            const __half* bg = Bg + (size_t)(kt+1)*32*N;
            cp16(sA[nb], ag); cp16(sA[nb]+16, ag+8);
            cp16(sB[nb], bg); cp16(sB[nb]+16, bg+8);
            cp_commit();
            cp_wait<1>();
        } else {
            cp_wait<0>();
        }
        __syncthreads();

#pragma unroll
        for (int ks=0; ks<32; ks+=16){
            uint32_t afr[4][4];
#pragma unroll
            for (int mt=0; mt<4; ++mt)
                ldm_x4(afr[mt], smem_u32(&As[buf][(a_r + mt*16)*AP + ks + a_c]));
            uint32_t bfr[2][4];
#pragma unroll
            for (int ng=0; ng<2; ++ng)
                ldm_x4t(bfr[ng], smem_u32(&Bs[buf][(ks + b_k)*BP + b_n + ng*16]));
#pragma unroll
            for (int mt=0; mt<4; ++mt)
#pragma unroll
                for (int nt=0; nt<4; ++nt)
                    mma16816(acc[mt][nt], afr[mt], &bfr[nt>>1][(nt&1)*2]);
        }
        __syncthreads();
    }

    // epilogue
#pragma unroll
    for (int mt=0; mt<4; ++mt){
        const int row0 = blockIdx.y*128 + wm*64 + mt*16 + gr;
#pragma unroll
        for (int nt=0; nt<4; ++nt){
            const int col = blockIdx.x*128 + wn*32 + nt*8 + tig*2;
            float v0 = acc[mt][nt][0], v1 = acc[mt][nt][1];
            float v2 = acc[mt][nt][2], v3 = acc[mt][nt][3];
            if (BIAS){
                float b0 = bias[col], b1 = bias[col+1];
                v0 += b0; v1 += b1; v2 += b0; v3 += b1;
            }
            if (RELU){
                v0 = fmaxf(v0,0.f); v1 = fmaxf(v1,0.f);
                v2 = fmaxf(v2,0.f); v3 = fmaxf(v3,0.f);
            }
            if constexpr (sizeof(OutT) == 2){
                *reinterpret_cast<uint32_t*>((__half*)C + (size_t)row0*N + col)     = packh2(v0,v1);
                *reinterpret_cast<uint32_t*>((__half*)C + (size_t)(row0+8)*N + col) = packh2(v2,v3);
            } else {
                *reinterpret_cast<float2*>((float*)C + (size_t)row0*N + col)     = make_float2(v0,v1);
                *reinterpret_cast<float2*>((float*)C + (size_t)(row0+8)*N + col) = make_float2(v2,v3);
            }
        }
    }
}

// ---------------------------------------------------------------------------
// RoPE in-place on half [BL, DD] laid out (b,l,h,d)
// ---------------------------------------------------------------------------
__global__ void rope_h(__half* __restrict__ t){
    int idx = blockIdx.x*blockDim.x + threadIdx.x;
    if (idx >= BL*NH*32) return;
    int i = idx & 31;
    int h = (idx>>5) & (NH-1);
    int row = idx >> 9;
    int l = row & (LL-1);
    float inv = powf(10000.f, -(float)(2*i)/(float)DK);
    float fr = (float)l * inv;
    float s, c; sincosf(fr, &s, &c);
    __half* base = t + (size_t)row*DD + h*DK;
    float x1 = __half2float(base[i]);
    float x2 = __half2float(base[i+32]);
    base[i]    = __float2half_rn(x1*c - x2*s);
    base[i+32] = __float2half_rn(x1*s + x2*c);
}

// ---------------------------------------------------------------------------
// fp16 flash attention, mma pipeline. grid (LL/64, BB*NH), 128 thr (4 warps).
// Q pre-scaled by (1/sqrt(dk))*log2(e); softmax in base-2.
// ---------------------------------------------------------------------------
#define FP 72  // padded smem row stride (halves)

__device__ __forceinline__ void flash_load_kv(const __half* __restrict__ K,
    const __half* __restrict__ V, size_t base, int kt,
    __half* ks, __half* vs, int tid)
{
#pragma unroll
    for (int c0=0;c0<4;c0++){
        int c = tid + c0*128;
        int r = c>>3, cu = (c&7)*8;
        size_t g = base + (size_t)(kt*64 + r)*DD + cu;
        cp16(smem_u32(ks + r*FP + cu), K+g);
        cp16(smem_u32(vs + r*FP + cu), V+g);
    }
}

__global__ void __launch_bounds__(128,1) flash_h(const __half* __restrict__ Q,
    const __half* __restrict__ K, const __half* __restrict__ V, __half* __restrict__ O)
{
    __shared__ __half Qs[64*FP];
    __shared__ __half Ks[2][64*FP];
    __shared__ __half Vs[2][64*FP];

    const int qt = blockIdx.x, bh = blockIdx.y;
    const int b = bh >> 4, h = bh & 15;
    const size_t base = (size_t)b*LL*DD + (size_t)h*DK;
    const int tid = threadIdx.x, warp = tid>>5, lane = tid&31;
    const int gr = lane>>2, tig = lane&3;

    // kick off KV tile 0 first (overlap with Q staging)
    flash_load_kv(K, V, base, 0, Ks[0], Vs[0], tid);
    cp_commit();

    // stage Q (scaled by 0.125 * log2(e))
    const float qsc = 0.125f * 1.4426950408889634f;
#pragma unroll
    for (int c0=0;c0<4;c0++){
        int c = tid + c0*128;
        int r = c>>3, cu = (c&7)*8;
        uint4 raw = *(const uint4*)(Q + base + (size_t)(qt*64 + r)*DD + cu);
        __half2* hp = (__half2*)&raw;
#pragma unroll
        for (int j=0;j<4;j++){
            float2 f = __half22float2(hp[j]);
            hp[j] = __floats2half2_rn(f.x*qsc, f.y*qsc);
        }
        *(uint4*)&Qs[r*FP + cu] = raw;
    }
    __syncthreads();

    // Q fragments (held in registers for whole loop)
    uint32_t qa[4][4];
    {
        const int qr = warp*16 + (lane&15);
        const int qc = (lane>>4)*8;
#pragma unroll
        for (int kb=0; kb<4; ++kb)
            ldm_x4(qa[kb], smem_u32(&Qs[qr*FP + kb*16 + qc]));
    }

    float m0 = -1e30f, m1 = -1e30f, l0 = 0.f, l1 = 0.f;
    float oc[8][4];
#pragma unroll
    for (int d=0; d<8; ++d)
#pragma unroll
        for (int t=0; t<4; ++t) oc[d][t] = 0.f;

    const int k_n = (lane&7) + ((lane>>4)&1)*8;   // K-frag (non-trans): key-row offset
    const int k_c = ((lane>>3)&1)*8;              // K-frag: dk-col offset
    const int v_k = (lane&7) + ((lane>>3)&1)*8;   // V-frag (trans): key-row offset
    const int v_n = ((lane>>4)&1)*8;              // V-frag: dv-col offset

    for (int kt=0; kt<LL/64; ++kt){
        const int buf = kt&1;
        if (kt+1 < LL/64){
            flash_load_kv(K, V, base, kt+1, Ks[buf^1], Vs[buf^1], tid);
            cp_commit();
            cp_wait<1>();
        } else {
            cp_wait<0>();
        }
        __syncthreads();

        // S = Q @ K^T  (warp: 16 x 64)
        float s[8][4];
#pragma unroll
        for (int nt=0; nt<8; ++nt)
#pragma unroll
            for (int t=0; t<4; ++t) s[nt][t] = 0.f;
#pragma unroll
        for (int kb=0; kb<4; ++kb){
#pragma unroll
            for (int ng=0; ng<4; ++ng){
                uint32_t kf[4];
                ldm_x4(kf, smem_u32(&Ks[buf][(ng*16 + k_n)*FP + kb*16 + k_c]));
                mma16816(s[2*ng],   qa[kb], kf);
                mma16816(s[2*ng+1], qa[kb], kf+2);
            }
        }

        // online softmax (base-2)
        float mx0 = -1e30f, mx1 = -1e30f;
#pragma unroll
        for (int nt=0; nt<8; ++nt){
            mx0 = fmaxf(mx0, fmaxf(s[nt][0], s[nt][1]));
            mx1 = fmaxf(mx1, fmaxf(s[nt][2], s[nt][3]));
        }
        mx0 = fmaxf(mx0, __shfl_xor_sync(0xffffffffu, mx0, 1));
        mx0 = fmaxf(mx0, __shfl_xor_sync(0xffffffffu, mx0, 2));
        mx1 = fmaxf(mx1, __shfl_xor_sync(0xffffffffu, mx1, 1));
        mx1 = fmaxf(mx1, __shfl_xor_sync(0xffffffffu, mx1, 2));

        float mn0 = fmaxf(m0, mx0), mn1 = fmaxf(m1, mx1);
        float f0 = exp2f(m0 - mn0), f1 = exp2f(m1 - mn1);
        m0 = mn0; m1 = mn1;

        float r0 = 0.f, r1 = 0.f;
#pragma unroll
        for (int nt=0; nt<8; ++nt){
            s[nt][0] = exp2f(s[nt][0] - mn0);
            s[nt][1] = exp2f(s[nt][1] - mn0);
            s[nt][2] = exp2f(s[nt][2] - mn1);
            s[nt][3] = exp2f(s[nt][3] - mn1);
            r0 += s[nt][0] + s[nt][1];
            r1 += s[nt][2] + s[nt][3];
        }
        r0 += __shfl_xor_sync(0xffffffffu, r0, 1);
        r0 += __shfl_xor_sync(0xffffffffu, r0, 2);
        r1 += __shfl_xor_sync(0xffffffffu, r1, 1);
        r1 += __shfl_xor_sync(0xffffffffu, r1, 2);
        l0 = l0*f0 + r0; l1 = l1*f1 + r1;

#pragma unroll
        for (int d=0; d<8; ++d){
            oc[d][0] *= f0; oc[d][1] *= f0;
            oc[d][2] *= f1; oc[d][3] *= f1;
        }

        // P fragments (A operand of PV)
        uint32_t pa[4][4];
#pragma unroll
        for (int kb=0; kb<4; ++kb){
            pa[kb][0] = packh2(s[2*kb][0],   s[2*kb][1]);
            pa[kb][1] = packh2(s[2*kb][2],   s[2*kb][3]);
            pa[kb][2] = packh2(s[2*kb+1][0], s[2*kb+1][1]);
            pa[kb][3] = packh2(s[2*kb+1][2], s[2*kb+1][3]);
        }

        // O += P @ V
#pragma unroll
        for (int kb=0; kb<4; ++kb){
#pragma unroll
            for (int ng=0; ng<4; ++ng){
                uint32_t vf[4];
                ldm_x4t(vf, smem_u32(&Vs[buf][(kb*16 + v_k)*FP + ng*16 + v_n]));
                mma16816(oc[2*ng],   pa[kb], vf);
                mma16816(oc[2*ng+1], pa[kb], vf+2);
            }
        }
        __syncthreads();
    }

    const float i0 = 1.f/l0, i1 = 1.f/l1;
    const int r0g = qt*64 + warp*16 + gr;
#pragma unroll
    for (int d=0; d<8; ++d){
        const int col = d*8 + tig*2;
        *reinterpret_cast<uint32_t*>(O + base + (size_t)r0g*DD + col)     = packh2(oc[d][0]*i0, oc[d][1]*i0);
        *reinterpret_cast<uint32_t*>(O + base + (size_t)(r0g+8)*DD + col) = packh2(oc[d][2]*i1, oc[d][3]*i1);
    }
}

// ---------------------------------------------------------------------------
// out = LayerNorm(a+b); optionally also write half copy
// ---------------------------------------------------------------------------
template<bool DUAL>
__global__ void add_ln(const float* __restrict__ a, const float* __restrict__ b,
                       const float* __restrict__ gamma, const float* __restrict__ beta,
                       float* __restrict__ o, __half* __restrict__ o2)
{
    const int row = blockIdx.x;
    const int tid = threadIdx.x;
    const float* pa = a + (size_t)row*DD;
    const float* pb = b + (size_t)row*DD;

    float v[4];
    float s = 0.f;
#pragma unroll
    for (int i=0;i<4;i++){
        int c = tid + i*256;
        v[i] = pa[c] + pb[c];
        s += v[i];
    }

    __shared__ float red[8];
    __shared__ float smean, srstd;
#pragma unroll
    for (int off=16; off; off>>=1) s += __shfl_xor_sync(0xffffffffu, s, off);
    if ((tid&31)==0) red[tid>>5] = s;
    __syncthreads();
    if (tid==0){
        float t=0.f;
#pragma unroll
        for (int i=0;i<8;i++) t += red[i];
        smean = t * (1.f/(float)DD);
    }
    __syncthreads();
    float mean = smean;

    float s2 = 0.f;
#pragma unroll
    for (int i=0;i<4;i++){ float d = v[i]-mean; s2 += d*d; }
#pragma unroll
    for (int off=16; off; off>>=1) s2 += __shfl_xor_sync(0xffffffffu, s2, off);
    if ((tid&31)==0) red[tid>>5] = s2;
    __syncthreads();
    if (tid==0){
        float t=0.f;
#pragma unroll
        for (int i=0;i<8;i++) t += red[i];
        srstd = rsqrtf(t * (1.f/(float)DD) + 1e-6f);
    }
    __syncthreads();
    float rstd = srstd;

    float* po = o + (size_t)row*DD;
#pragma unroll
    for (int i=0;i<4;i++){
        int c = tid + i*256;
        float r = gamma[c]*(v[i]-mean)*rstd + beta[c];
        po[c] = r;
        if (DUAL) o2[(size_t)row*DD + c] = __float2half_rn(r);
    }
}

// ---------------------------------------------------------------------------
// Launch
// ---------------------------------------------------------------------------
extern "C" void kernel_launch(void* const* d_in, const int* in_sizes, int n_in,
                              void* d_out, int out_size) {
    const float* x      = (const float*)d_in[0];
    const float* w_q    = (const float*)d_in[1];
    const float* w_k    = (const float*)d_in[2];
    const float* w_v    = (const float*)d_in[3];
    const float* w_o    = (const float*)d_in[4];
    const float* b_o    = (const float*)d_in[5];
    const float* gamma1 = (const float*)d_in[6];
    const float* beta1  = (const float*)d_in[7];
    const float* gamma2 = (const float*)d_in[8];
    const float* beta2  = (const float*)d_in[9];
    const float* w1     = (const float*)d_in[10];
    const float* b1     = (const float*)d_in[11];
    const float* w2     = (const float*)d_in[12];
    const float* b2     = (const float*)d_in[13];
    float* out = (float*)d_out;

    __half* hbase = nullptr;  float* fbase = nullptr;
    cudaGetSymbolAddress((void**)&hbase, g_h);
    cudaGetSymbolAddress((void**)&fbase, g_f);

    const size_t M1 = (size_t)BL*DD;        // 4M
    const size_t W  = (size_t)DD*DD;        // 1M
    const size_t W1 = (size_t)DD*FF;        // 4M
    const size_t F1 = (size_t)BL*FF;        // 16M

    __half* xh  = hbase;
    __half* q   = xh  + M1;
    __half* k   = q   + M1;
    __half* v   = k   + M1;
    __half* ctx = v   + M1;
    __half* hh  = ctx + M1;
    __half* ff1 = hh  + M1;
    __half* wqh = ff1 + F1;
    __half* wkh = wqh + W;
    __half* wvh = wkh + W;
    __half* woh = wvh + W;
    __half* w1h = woh + W;
    __half* w2h = w1h + W1;

    float* attnf = fbase;
    float* hbuf  = attnf + M1;
    float* ff2f  = hbuf  + M1;

    dim3 blk256(256);
    // conversions
    f2h<<<(int)((M1/4+255)/256), blk256>>>(x,   xh,  (int)M1);
    f2h<<<(int)((W /4+255)/256), blk256>>>(w_q, wqh, (int)W);
    f2h<<<(int)((W /4+255)/256), blk256>>>(w_k, wkh, (int)W);
    f2h<<<(int)((W /4+255)/256), blk256>>>(w_v, wvh, (int)W);
    f2h<<<(int)((W /4+255)/256), blk256>>>(w_o, woh, (int)W);
    f2h<<<(int)((W1/4+255)/256), blk256>>>(w1,  w1h, (int)W1);
    f2h<<<(int)((W1/4+255)/256), blk256>>>(w2,  w2h, (int)W1);

    // QKV projections
    dim3 gproj(DD/128, BL/128);
    hgemm<__half,false,false><<<gproj, blk256>>>(xh, wqh, nullptr, q, BL, DD, DD);
    hgemm<__half,false,false><<<gproj, blk256>>>(xh, wkh, nullptr, k, BL, DD, DD);
    hgemm<__half,false,false><<<gproj, blk256>>>(xh, wvh, nullptr, v, BL, DD, DD);

    // RoPE
    int rope_total = BL*NH*32;
    rope_h<<<(rope_total+255)/256, blk256>>>(q);
    rope_h<<<(rope_total+255)/256, blk256>>>(k);

    // attention
    dim3 gattn(LL/64, BB*NH);
    flash_h<<<gattn, dim3(128)>>>(q, k, v, ctx);

    // output projection (float out)
    hgemm<float,true,false><<<gproj, blk256>>>(ctx, woh, b_o, attnf, BL, DD, DD);

    // h = LN(x + attn): float + half
    add_ln<true><<<BL, blk256>>>(x, attnf, gamma1, beta1, hbuf, hh);

    // FFN
    dim3 gff1(FF/128, BL/128);
    hgemm<__half,true,true><<<gff1, blk256>>>(hh, w1h, b1, ff1, BL, FF, DD);
    dim3 gff2(DD/128, BL/128);
    hgemm<float,true,false><<<gff2, blk256>>>(ff1, w2h, b2, ff2f, BL, DD, FF);

    // out = LN(h + ff2)
    add_ln<false><<<BL, blk256>>>(hbuf, ff2f, gamma2, beta2, out, nullptr);
}

// round 4
// speedup vs baseline: 6.2473x; 1.1357x over previous
#include <cuda_runtime.h>
#include <cuda_fp16.h>
#include <math.h>
#include <stdint.h>

#define BB 2
#define LL 2048
#define DD 1024
#define FF 4096
#define NH 16
#define DK 64
#define BL (BB*LL)

// ---------------------------------------------------------------------------
// Scratch (device globals; no allocations allowed)
// ---------------------------------------------------------------------------
__device__ __half g_h[(size_t)6*BL*DD + (size_t)BL*FF + (size_t)4*DD*DD + (size_t)2*DD*FF];
__device__ float  g_f[(size_t)3*BL*DD];

// ---------------------------------------------------------------------------
// PTX helpers
// ---------------------------------------------------------------------------
__device__ __forceinline__ uint32_t smem_u32(const void* p){
    return (uint32_t)__cvta_generic_to_shared(p);
}
__device__ __forceinline__ void cp16(uint32_t s, const void* g){
    asm volatile("cp.async.cg.shared.global [%0], [%1], 16;\n" :: "r"(s), "l"(g));
}
__device__ __forceinline__ void cp_commit(){ asm volatile("cp.async.commit_group;\n"); }
template<int N> __device__ __forceinline__ void cp_wait(){
    asm volatile("cp.async.wait_group %0;\n" :: "n"(N));
}
__device__ __forceinline__ void ldm_x4(uint32_t* r, uint32_t addr){
    asm volatile("ldmatrix.sync.aligned.m8n8.x4.shared.b16 {%0,%1,%2,%3}, [%4];\n"
        : "=r"(r[0]),"=r"(r[1]),"=r"(r[2]),"=r"(r[3]) : "r"(addr));
}
__device__ __forceinline__ void ldm_x4t(uint32_t* r, uint32_t addr){
    asm volatile("ldmatrix.sync.aligned.m8n8.x4.trans.shared.b16 {%0,%1,%2,%3}, [%4];\n"
        : "=r"(r[0]),"=r"(r[1]),"=r"(r[2]),"=r"(r[3]) : "r"(addr));
}
__device__ __forceinline__ void mma16816(float* d, const uint32_t* a, const uint32_t* b){
    asm volatile("mma.sync.aligned.m16n8k16.row.col.f32.f16.f16.f32 "
        "{%0,%1,%2,%3}, {%4,%5,%6,%7}, {%8,%9}, {%0,%1,%2,%3};\n"
        : "+f"(d[0]),"+f"(d[1]),"+f"(d[2]),"+f"(d[3])
        : "r"(a[0]),"r"(a[1]),"r"(a[2]),"r"(a[3]), "r"(b[0]),"r"(b[1]));
}
__device__ __forceinline__ uint32_t packh2(float x, float y){
    __half2 h = __floats2half2_rn(x, y);
    return *reinterpret_cast<uint32_t*>(&h);
}

// ---------------------------------------------------------------------------
// fp32 -> fp16 conversion
// ---------------------------------------------------------------------------
__global__ void f2h(const float* __restrict__ s, __half* __restrict__ d, int n){
    int i = (blockIdx.x*blockDim.x + threadIdx.x)*4;
    if (i >= n) return;
    float4 f = *(const float4*)(s+i);
    __half2 lo = __floats2half2_rn(f.x, f.y);
    __half2 hi = __floats2half2_rn(f.z, f.w);
    uint2 u; u.x = *reinterpret_cast<uint32_t*>(&lo); u.y = *reinterpret_cast<uint32_t*>(&hi);
    *(uint2*)(d+i) = u;
}

// ---------------------------------------------------------------------------
// fp16 GEMM v2: C[M,N] = A[M,K] @ B[K,N] (+bias)(+relu), fp32 accum
// 128x128x64 tile, 3-stage cp.async pipeline, 256 thr (8 warps 2x4)
// ---------------------------------------------------------------------------
#define AP2 72      // A smem row stride (halves): 64 data + 8 pad
#define BP2 136     // B smem row stride (halves): 128 data + 8 pad
#define ASTG (128*AP2)   // halves per A stage = 9216
#define BSTG (64*BP2)    // halves per B stage = 8704
#define GSTAGES 3
#define GSMEM ((ASTG + BSTG) * GSTAGES * 2)   // bytes = 107520

__device__ __forceinline__ void g_load(const __half* __restrict__ Ag,
    const __half* __restrict__ Bg, int kt, __half* As, __half* Bs,
    int K, int N, int tid)
{
    const __half* a = Ag + (size_t)kt*64;
    const __half* b = Bg + (size_t)kt*64*N;
#pragma unroll
    for (int i=0;i<4;i++){
        int c = tid + i*256;
        int r = c>>3, k16 = c&7;
        cp16(smem_u32(As + r*AP2 + k16*8), a + (size_t)r*K + k16*8);
    }
#pragma unroll
    for (int i=0;i<4;i++){
        int c = tid + i*256;
        int r = c>>4, n16 = c&15;
        cp16(smem_u32(Bs + r*BP2 + n16*8), b + (size_t)r*N + n16*8);
    }
}

template<typename OutT, bool BIAS, bool RELU>
__global__ void __launch_bounds__(256,1) hgemm2(const __half* __restrict__ A,
    const __half* __restrict__ Bm, const float* __restrict__ bias,
    OutT* __restrict__ C, int M, int N, int K)
{
    extern __shared__ __align__(16) __half sm2[];
    __half* As0 = sm2;                      // [3][ASTG]
    __half* Bs0 = sm2 + GSTAGES*ASTG;       // [3][BSTG]

    const int tid = threadIdx.x;
    const int warp = tid>>5, lane = tid&31;
    const int wm = warp>>2, wn = warp&3;
    const int gr = lane>>2, tig = lane&3;

    const __half* Ag = A + (size_t)(blockIdx.y*128)*K;
    const __half* Bg = Bm + blockIdx.x*128;

    const int a_r = wm*64 + (lane&15);
    const int a_c = (lane>>4)*8;
    const int b_k = (lane&7) + ((lane>>3)&1)*8;
    const int b_n = wn*32 + ((lane>>4)&1)*8;

    float acc[4][4][4];
#pragma unroll
    for (int i=0;i<4;i++)
#pragma unroll
        for (int j=0;j<4;j++)
#pragma unroll
            for (int t=0;t<4;t++) acc[i][j][t] = 0.f;

    const int NT = K>>6;
    // prologue: tiles 0,1
    g_load(Ag, Bg, 0, As0, Bs0, K, N, tid); cp_commit();
    if (NT > 1){ g_load(Ag, Bg, 1, As0 + ASTG, Bs0 + BSTG, K, N, tid); }
    cp_commit();

    int buf = 0;
    for (int kt=0; kt<NT; ++kt){
        if (kt == NT-1) cp_wait<0>(); else cp_wait<1>();
        __syncthreads();
        if (kt+2 < NT){
            int nb = buf+2; if (nb >= GSTAGES) nb -= GSTAGES;
            g_load(Ag, Bg, kt+2, As0 + nb*ASTG, Bs0 + nb*BSTG, K, N, tid);
            cp_commit();
        }

        const __half* As = As0 + buf*ASTG;
        const __half* Bs = Bs0 + buf*BSTG;
#pragma unroll
        for (int ks=0; ks<64; ks+=16){
            uint32_t afr[4][4];
#pragma unroll
            for (int mt=0; mt<4; ++mt)
                ldm_x4(afr[mt], smem_u32(As + (a_r + mt*16)*AP2 + ks + a_c));
            uint32_t bfr[2][4];
#pragma unroll
            for (int ng=0; ng<2; ++ng)
                ldm_x4t(bfr[ng], smem_u32(Bs + (ks + b_k)*BP2 + b_n + ng*16));
#pragma unroll
            for (int mt=0; mt<4; ++mt)
#pragma unroll
                for (int nt=0; nt<4; ++nt)
                    mma16816(acc[mt][nt], afr[mt], &bfr[nt>>1][(nt&1)*2]);
        }
        ++buf; if (buf >= GSTAGES) buf = 0;
    }

    // epilogue
#pragma unroll
    for (int mt=0; mt<4; ++mt){
        const int row0 = blockIdx.y*128 + wm*64 + mt*16 + gr;
#pragma unroll
        for (int nt=0; nt<4; ++nt){
            const int col = blockIdx.x*128 + wn*32 + nt*8 + tig*2;
            float v0 = acc[mt][nt][0], v1 = acc[mt][nt][1];
            float v2 = acc[mt][nt][2], v3 = acc[mt][nt][3];
            if (BIAS){
                float b0 = bias[col], b1 = bias[col+1];
                v0 += b0; v1 += b1; v2 += b0; v3 += b1;
            }
            if (RELU){
                v0 = fmaxf(v0,0.f); v1 = fmaxf(v1,0.f);
                v2 = fmaxf(v2,0.f); v3 = fmaxf(v3,0.f);
            }
            if constexpr (sizeof(OutT) == 2){
                *reinterpret_cast<uint32_t*>((__half*)C + (size_t)row0*N + col)     = packh2(v0,v1);
                *reinterpret_cast<uint32_t*>((__half*)C + (size_t)(row0+8)*N + col) = packh2(v2,v3);
            } else {
                *reinterpret_cast<float2*>((float*)C + (size_t)row0*N + col)     = make_float2(v0,v1);
                *reinterpret_cast<float2*>((float*)C + (size_t)(row0+8)*N + col) = make_float2(v2,v3);
            }
        }
    }
}

// ---------------------------------------------------------------------------
// RoPE in-place on half [BL, DD] laid out (b,l,h,d)
// ---------------------------------------------------------------------------
__global__ void rope_h(__half* __restrict__ t){
    int idx = blockIdx.x*blockDim.x + threadIdx.x;
    if (idx >= BL*NH*32) return;
    int i = idx & 31;
    int h = (idx>>5) & (NH-1);
    int row = idx >> 9;
    int l = row & (LL-1);
    float inv = powf(10000.f, -(float)(2*i)/(float)DK);
    float fr = (float)l * inv;
    float s, c; sincosf(fr, &s, &c);
    __half* base = t + (size_t)row*DD + h*DK;
    float x1 = __half2float(base[i]);
    float x2 = __half2float(base[i+32]);
    base[i]    = __float2half_rn(x1*c - x2*s);
    base[i+32] = __float2half_rn(x1*s + x2*c);
}

// ---------------------------------------------------------------------------
// flash attention v2: Q tile 128 (8 warps / 256 thr), 64-key tiles, dbl-buffer
// ---------------------------------------------------------------------------
#define FP 72
#define FSMEM ((128*FP + 4*64*FP) * 2)   // bytes = 55296

__device__ __forceinline__ void flash_load_kv(const __half* __restrict__ K,
    const __half* __restrict__ V, size_t base, int kt,
    __half* ks, __half* vs, int tid)
{
#pragma unroll
    for (int c0=0;c0<2;c0++){
        int c = tid + c0*256;
        int r = c>>3, cu = (c&7)*8;
        size_t g = base + (size_t)(kt*64 + r)*DD + cu;
        cp16(smem_u32(ks + r*FP + cu), K+g);
        cp16(smem_u32(vs + r*FP + cu), V+g);
    }
}

__global__ void __launch_bounds__(256,1) flash_h(const __half* __restrict__ Q,
    const __half* __restrict__ K, const __half* __restrict__ V, __half* __restrict__ O)
{
    extern __shared__ __align__(16) __half fsm[];
    __half* Qs = fsm;                 // 128*FP
    __half* Ks = Qs + 128*FP;         // 2 x 64*FP
    __half* Vs = Ks + 2*64*FP;        // 2 x 64*FP

    const int qt = blockIdx.x, bh = blockIdx.y;
    const int b = bh >> 4, h = bh & 15;
    const size_t base = (size_t)b*LL*DD + (size_t)h*DK;
    const int tid = threadIdx.x, warp = tid>>5, lane = tid&31;
    const int gr = lane>>2, tig = lane&3;

    flash_load_kv(K, V, base, 0, Ks, Vs, tid);
    cp_commit();

    const float qsc = 0.125f * 1.4426950408889634f;
#pragma unroll
    for (int c0=0;c0<4;c0++){
        int c = tid + c0*256;
        int r = c>>3, cu = (c&7)*8;
        uint4 raw = *(const uint4*)(Q + base + (size_t)(qt*128 + r)*DD + cu);
        __half2* hp = (__half2*)&raw;
#pragma unroll
        for (int j=0;j<4;j++){
            float2 f = __half22float2(hp[j]);
            hp[j] = __floats2half2_rn(f.x*qsc, f.y*qsc);
        }
        *(uint4*)&Qs[r*FP + cu] = raw;
    }
    __syncthreads();

    uint32_t qa[4][4];
    {
        const int qr = warp*16 + (lane&15);
        const int qc = (lane>>4)*8;
#pragma unroll
        for (int kb=0; kb<4; ++kb)
            ldm_x4(qa[kb], smem_u32(&Qs[qr*FP + kb*16 + qc]));
    }

    float m0 = -1e30f, m1 = -1e30f, l0 = 0.f, l1 = 0.f;
    float oc[8][4];
#pragma unroll
    for (int d=0; d<8; ++d)
#pragma unroll
        for (int t=0; t<4; ++t) oc[d][t] = 0.f;

    const int k_n = (lane&7) + ((lane>>4)&1)*8;
    const int k_c = ((lane>>3)&1)*8;
    const int v_k = (lane&7) + ((lane>>3)&1)*8;
    const int v_n = ((lane>>4)&1)*8;

    for (int kt=0; kt<LL/64; ++kt){
        const int buf = kt&1;
        if (kt+1 < LL/64){
            flash_load_kv(K, V, base, kt+1, Ks + (buf^1)*64*FP, Vs + (buf^1)*64*FP, tid);
            cp_commit();
            cp_wait<1>();
        } else {
            cp_wait<0>();
        }
        __syncthreads();

        const __half* kbuf = Ks + buf*64*FP;
        const __half* vbuf = Vs + buf*64*FP;

        float s[8][4];
#pragma unroll
        for (int nt=0; nt<8; ++nt)
#pragma unroll
            for (int t=0; t<4; ++t) s[nt][t] = 0.f;
#pragma unroll
        for (int kb=0; kb<4; ++kb){
#pragma unroll
            for (int ng=0; ng<4; ++ng){
                uint32_t kf[4];
                ldm_x4(kf, smem_u32(kbuf + (ng*16 + k_n)*FP + kb*16 + k_c));
                mma16816(s[2*ng],   qa[kb], kf);
                mma16816(s[2*ng+1], qa[kb], kf+2);
            }
        }

        float mx0 = -1e30f, mx1 = -1e30f;
#pragma unroll
        for (int nt=0; nt<8; ++nt){
            mx0 = fmaxf(mx0, fmaxf(s[nt][0], s[nt][1]));
            mx1 = fmaxf(mx1, fmaxf(s[nt][2], s[nt][3]));
        }
        mx0 = fmaxf(mx0, __shfl_xor_sync(0xffffffffu, mx0, 1));
        mx0 = fmaxf(mx0, __shfl_xor_sync(0xffffffffu, mx0, 2));
        mx1 = fmaxf(mx1, __shfl_xor_sync(0xffffffffu, mx1, 1));
        mx1 = fmaxf(mx1, __shfl_xor_sync(0xffffffffu, mx1, 2));

        float mn0 = fmaxf(m0, mx0), mn1 = fmaxf(m1, mx1);
        float f0 = exp2f(m0 - mn0), f1 = exp2f(m1 - mn1);
        m0 = mn0; m1 = mn1;

        float r0 = 0.f, r1 = 0.f;
#pragma unroll
        for (int nt=0; nt<8; ++nt){
            s[nt][0] = exp2f(s[nt][0] - mn0);
            s[nt][1] = exp2f(s[nt][1] - mn0);
            s[nt][2] = exp2f(s[nt][2] - mn1);
            s[nt][3] = exp2f(s[nt][3] - mn1);
            r0 += s[nt][0] + s[nt][1];
            r1 += s[nt][2] + s[nt][3];
        }
        r0 += __shfl_xor_sync(0xffffffffu, r0, 1);
        r0 += __shfl_xor_sync(0xffffffffu, r0, 2);
        r1 += __shfl_xor_sync(0xffffffffu, r1, 1);
        r1 += __shfl_xor_sync(0xffffffffu, r1, 2);
        l0 = l0*f0 + r0; l1 = l1*f1 + r1;

#pragma unroll
        for (int d=0; d<8; ++d){
            oc[d][0] *= f0; oc[d][1] *= f0;
            oc[d][2] *= f1; oc[d][3] *= f1;
        }

        uint32_t pa[4][4];
#pragma unroll
        for (int kb=0; kb<4; ++kb){
            pa[kb][0] = packh2(s[2*kb][0],   s[2*kb][1]);
            pa[kb][1] = packh2(s[2*kb][2],   s[2*kb][3]);
            pa[kb][2] = packh2(s[2*kb+1][0], s[2*kb+1][1]);
            pa[kb][3] = packh2(s[2*kb+1][2], s[2*kb+1][3]);
        }

#pragma unroll
        for (int kb=0; kb<4; ++kb){
#pragma unroll
            for (int ng=0; ng<4; ++ng){
                uint32_t vf[4];
                ldm_x4t(vf, smem_u32(vbuf + (kb*16 + v_k)*FP + ng*16 + v_n));
                mma16816(oc[2*ng],   pa[kb], vf);
                mma16816(oc[2*ng+1], pa[kb], vf+2);
            }
        }
        __syncthreads();
    }

    const float i0 = 1.f/l0, i1 = 1.f/l1;
    const int r0g = qt*128 + warp*16 + gr;
#pragma unroll
    for (int d=0; d<8; ++d){
        const int col = d*8 + tig*2;
        *reinterpret_cast<uint32_t*>(O + base + (size_t)r0g*DD + col)     = packh2(oc[d][0]*i0, oc[d][1]*i0);
        *reinterpret_cast<uint32_t*>(O + base + (size_t)(r0g+8)*DD + col) = packh2(oc[d][2]*i1, oc[d][3]*i1);
    }
}

// ---------------------------------------------------------------------------
// out = LayerNorm(a+b); optionally also write half copy
// ---------------------------------------------------------------------------
template<bool DUAL>
__global__ void add_ln(const float* __restrict__ a, const float* __restrict__ b,
                       const float* __restrict__ gamma, const float* __restrict__ beta,
                       float* __restrict__ o, __half* __restrict__ o2)
{
    const int row = blockIdx.x;
    const int tid = threadIdx.x;
    const float* pa = a + (size_t)row*DD;
    const float* pb = b + (size_t)row*DD;

    float v[4];
    float s = 0.f;
#pragma unroll
    for (int i=0;i<4;i++){
        int c = tid + i*256;
        v[i] = pa[c] + pb[c];
        s += v[i];
    }

    __shared__ float red[8];
    __shared__ float smean, srstd;
#pragma unroll
    for (int off=16; off; off>>=1) s += __shfl_xor_sync(0xffffffffu, s, off);
    if ((tid&31)==0) red[tid>>5] = s;
    __syncthreads();
    if (tid==0){
        float t=0.f;
#pragma unroll
        for (int i=0;i<8;i++) t += red[i];
        smean = t * (1.f/(float)DD);
    }
    __syncthreads();
    float mean = smean;

    float s2 = 0.f;
#pragma unroll
    for (int i=0;i<4;i++){ float d = v[i]-mean; s2 += d*d; }
#pragma unroll
    for (int off=16; off; off>>=1) s2 += __shfl_xor_sync(0xffffffffu, s2, off);
    if ((tid&31)==0) red[tid>>5] = s2;
    __syncthreads();
    if (tid==0){
        float t=0.f;
#pragma unroll
        for (int i=0;i<8;i++) t += red[i];
        srstd = rsqrtf(t * (1.f/(float)DD) + 1e-6f);
    }
    __syncthreads();
    float rstd = srstd;

    float* po = o + (size_t)row*DD;
#pragma unroll
    for (int i=0;i<4;i++){
        int c = tid + i*256;
        float r = gamma[c]*(v[i]-mean)*rstd + beta[c];
        po[c] = r;
        if (DUAL) o2[(size_t)row*DD + c] = __float2half_rn(r);
    }
}

// ---------------------------------------------------------------------------
// Launch
// ---------------------------------------------------------------------------
extern "C" void kernel_launch(void* const* d_in, const int* in_sizes, int n_in,
                              void* d_out, int out_size) {
    const float* x      = (const float*)d_in[0];
    const float* w_q    = (const float*)d_in[1];
    const float* w_k    = (const float*)d_in[2];
    const float* w_v    = (const float*)d_in[3];
    const float* w_o    = (const float*)d_in[4];
    const float* b_o    = (const float*)d_in[5];
    const float* gamma1 = (const float*)d_in[6];
    const float* beta1  = (const float*)d_in[7];
    const float* gamma2 = (const float*)d_in[8];
    const float* beta2  = (const float*)d_in[9];
    const float* w1     = (const float*)d_in[10];
    const float* b1     = (const float*)d_in[11];
    const float* w2     = (const float*)d_in[12];
    const float* b2     = (const float*)d_in[13];
    float* out = (float*)d_out;

    __half* hbase = nullptr;  float* fbase = nullptr;
    cudaGetSymbolAddress((void**)&hbase, g_h);
    cudaGetSymbolAddress((void**)&fbase, g_f);

    const size_t M1 = (size_t)BL*DD;
    const size_t W  = (size_t)DD*DD;
    const size_t W1 = (size_t)DD*FF;
    const size_t F1 = (size_t)BL*FF;

    __half* xh  = hbase;
    __half* q   = xh  + M1;
    __half* k   = q   + M1;
    __half* v   = k   + M1;
    __half* ctx = v   + M1;
    __half* hh  = ctx + M1;
    __half* ff1 = hh  + M1;
    __half* wqh = ff1 + F1;
    __half* wkh = wqh + W;
    __half* wvh = wkh + W;
    __half* woh = wvh + W;
    __half* w1h = woh + W;
    __half* w2h = w1h + W1;

    float* attnf = fbase;
    float* hbuf  = attnf + M1;
    float* ff2f  = hbuf  + M1;

    cudaFuncSetAttribute(hgemm2<__half,false,false>, cudaFuncAttributeMaxDynamicSharedMemorySize, GSMEM);
    cudaFuncSetAttribute(hgemm2<float, true, false>, cudaFuncAttributeMaxDynamicSharedMemorySize, GSMEM);
    cudaFuncSetAttribute(hgemm2<__half,true, true >, cudaFuncAttributeMaxDynamicSharedMemorySize, GSMEM);
    cudaFuncSetAttribute(flash_h, cudaFuncAttributeMaxDynamicSharedMemorySize, FSMEM);

    dim3 blk256(256);
    // conversions
    f2h<<<(int)((M1/4+255)/256), blk256>>>(x,   xh,  (int)M1);
    f2h<<<(int)((W /4+255)/256), blk256>>>(w_q, wqh, (int)W);
    f2h<<<(int)((W /4+255)/256), blk256>>>(w_k, wkh, (int)W);
    f2h<<<(int)((W /4+255)/256), blk256>>>(w_v, wvh, (int)W);
    f2h<<<(int)((W /4+255)/256), blk256>>>(w_o, woh, (int)W);
    f2h<<<(int)((W1/4+255)/256), blk256>>>(w1,  w1h, (int)W1);
    f2h<<<(int)((W1/4+255)/256), blk256>>>(w2,  w2h, (int)W1);

    // QKV projections
    dim3 gproj(DD/128, BL/128);
    hgemm2<__half,false,false><<<gproj, blk256, GSMEM>>>(xh, wqh, nullptr, q, BL, DD, DD);
    hgemm2<__half,false,false><<<gproj, blk256, GSMEM>>>(xh, wkh, nullptr, k, BL, DD, DD);
    hgemm2<__half,false,false><<<gproj, blk256, GSMEM>>>(xh, wvh, nullptr, v, BL, DD, DD);

    // RoPE
    int rope_total = BL*NH*32;
    rope_h<<<(rope_total+255)/256, blk256>>>(q);
    rope_h<<<(rope_total+255)/256, blk256>>>(k);

    // attention
    dim3 gattn(LL/128, BB*NH);
    flash_h<<<gattn, blk256, FSMEM>>>(q, k, v, ctx);

    // output projection
    hgemm2<float,true,false><<<gproj, blk256, GSMEM>>>(ctx, woh, b_o, attnf, BL, DD, DD);

    // h = LN(x + attn)
    add_ln<true><<<BL, blk256>>>(x, attnf, gamma1, beta1, hbuf, hh);

    // FFN
    dim3 gff1(FF/128, BL/128);
    hgemm2<__half,true,true><<<gff1, blk256, GSMEM>>>(hh, w1h, b1, ff1, BL, FF, DD);
    dim3 gff2(DD/128, BL/128);
    hgemm2<float,true,false><<<gff2, blk256, GSMEM>>>(ff1, w2h, b2, ff2f, BL, DD, FF);

    // out = LN(h + ff2)
    add_ln<false><<<BL, blk256>>>(hbuf, ff2f, gamma2, beta2, out, nullptr);
}

// round 5
// speedup vs baseline: 6.2840x; 1.0059x over previous
#include <cuda_runtime.h>
#include <cuda_fp16.h>
#include <math.h>
#include <stdint.h>

#define BB 2
#define LL 2048
#define DD 1024
#define FF 4096
#define NH 16
#define DK 64
#define BL (BB*LL)

// ---------------------------------------------------------------------------
// Scratch (device globals; no allocations allowed)
// ---------------------------------------------------------------------------
__device__ __half g_h[(size_t)6*BL*DD + (size_t)BL*FF + (size_t)4*DD*DD + (size_t)2*DD*FF];
__device__ float  g_f[(size_t)3*BL*DD];

// ---------------------------------------------------------------------------
// PTX helpers
// ---------------------------------------------------------------------------
__device__ __forceinline__ uint32_t smem_u32(const void* p){
    return (uint32_t)__cvta_generic_to_shared(p);
}
__device__ __forceinline__ void cp16(uint32_t s, const void* g){
    asm volatile("cp.async.cg.shared.global [%0], [%1], 16;\n" :: "r"(s), "l"(g));
}
__device__ __forceinline__ void cp_commit(){ asm volatile("cp.async.commit_group;\n"); }
template<int N> __device__ __forceinline__ void cp_wait(){
    asm volatile("cp.async.wait_group %0;\n" :: "n"(N));
}
__device__ __forceinline__ void ldm_x4(uint32_t* r, uint32_t addr){
    asm volatile("ldmatrix.sync.aligned.m8n8.x4.shared.b16 {%0,%1,%2,%3}, [%4];\n"
        : "=r"(r[0]),"=r"(r[1]),"=r"(r[2]),"=r"(r[3]) : "r"(addr));
}
__device__ __forceinline__ void ldm_x4t(uint32_t* r, uint32_t addr){
    asm volatile("ldmatrix.sync.aligned.m8n8.x4.trans.shared.b16 {%0,%1,%2,%3}, [%4];\n"
        : "=r"(r[0]),"=r"(r[1]),"=r"(r[2]),"=r"(r[3]) : "r"(addr));
}
__device__ __forceinline__ void mma16816(float* d, const uint32_t* a, const uint32_t* b){
    asm volatile("mma.sync.aligned.m16n8k16.row.col.f32.f16.f16.f32 "
        "{%0,%1,%2,%3}, {%4,%5,%6,%7}, {%8,%9}, {%0,%1,%2,%3};\n"
        : "+f"(d[0]),"+f"(d[1]),"+f"(d[2]),"+f"(d[3])
        : "r"(a[0]),"r"(a[1]),"r"(a[2]),"r"(a[3]), "r"(b[0]),"r"(b[1]));
}
__device__ __forceinline__ uint32_t packh2(float x, float y){
    __half2 h = __floats2half2_rn(x, y);
    return *reinterpret_cast<uint32_t*>(&h);
}

// ---------------------------------------------------------------------------
// conversions
// ---------------------------------------------------------------------------
__global__ void f2h(const float* __restrict__ s, __half* __restrict__ d, int n){
    int i = (blockIdx.x*blockDim.x + threadIdx.x)*4;
    if (i >= n) return;
    float4 f = *(const float4*)(s+i);
    __half2 lo = __floats2half2_rn(f.x, f.y);
    __half2 hi = __floats2half2_rn(f.z, f.w);
    uint2 u; u.x = *reinterpret_cast<uint32_t*>(&lo); u.y = *reinterpret_cast<uint32_t*>(&hi);
    *(uint2*)(d+i) = u;
}

// 3x [DD,DD] f32 -> concat [DD, 3*DD] f16 (column blocks)
__global__ void f2h3(const float* __restrict__ a, const float* __restrict__ b,
                     const float* __restrict__ c, __half* __restrict__ d){
    int i = (blockIdx.x*blockDim.x + threadIdx.x)*4;
    if (i >= DD*DD) return;
    int kk = i >> 10, n = i & (DD-1);
    const float* srcs[3] = {a, b, c};
#pragma unroll
    for (int t=0;t<3;t++){
        float4 f = *(const float4*)(srcs[t]+i);
        __half2 lo = __floats2half2_rn(f.x, f.y);
        __half2 hi = __floats2half2_rn(f.z, f.w);
        uint2 u; u.x = *reinterpret_cast<uint32_t*>(&lo); u.y = *reinterpret_cast<uint32_t*>(&hi);
        *(uint2*)(d + (size_t)kk*3*DD + t*DD + n) = u;
    }
}

// ---------------------------------------------------------------------------
// fp16 GEMM: C[M,N] = A[M,K] @ B[K,N] (+bias)(+relu), fp32 accum
// 128x128x64 tile, 4-stage cp.async pipeline, 256 thr (8 warps 2x4)
// NSPLIT=3: route 128-col tiles to C0/C1/C2 (each N/3 wide)
// ---------------------------------------------------------------------------
#define AP2 72
#define BP2 136
#define ASTG (128*AP2)
#define BSTG (64*BP2)
#define GSTAGES 4
#define GSMEM ((ASTG + BSTG) * GSTAGES * 2)   // 143360 bytes

__device__ __forceinline__ void g_load(const __half* __restrict__ Ag,
    const __half* __restrict__ Bg, int kt, __half* As, __half* Bs,
    int K, int N, int tid)
{
    const __half* a = Ag + (size_t)kt*64;
    const __half* b = Bg + (size_t)kt*64*N;
#pragma unroll
    for (int i=0;i<4;i++){
        int c = tid + i*256;
        int r = c>>3, k16 = c&7;
        cp16(smem_u32(As + r*AP2 + k16*8), a + (size_t)r*K + k16*8);
    }
#pragma unroll
    for (int i=0;i<4;i++){
        int c = tid + i*256;
        int r = c>>4, n16 = c&15;
        cp16(smem_u32(Bs + r*BP2 + n16*8), b + (size_t)r*N + n16*8);
    }
}

template<typename OutT, bool BIAS, bool RELU, int NSPLIT>
__global__ void __launch_bounds__(256,1) hgemm2(const __half* __restrict__ A,
    const __half* __restrict__ Bm, const float* __restrict__ bias,
    OutT* __restrict__ C0, OutT* __restrict__ C1, OutT* __restrict__ C2,
    int M, int N, int K)
{
    extern __shared__ __align__(16) __half sm2[];
    __half* As0 = sm2;
    __half* Bs0 = sm2 + GSTAGES*ASTG;

    const int tid = threadIdx.x;
    const int warp = tid>>5, lane = tid&31;
    const int wm = warp>>2, wn = warp&3;
    const int gr = lane>>2, tig = lane&3;

    const __half* Ag = A + (size_t)(blockIdx.y*128)*K;
    const __half* Bg = Bm + blockIdx.x*128;

    const int a_r = wm*64 + (lane&15);
    const int a_c = (lane>>4)*8;
    const int b_k = (lane&7) + ((lane>>3)&1)*8;
    const int b_n = wn*32 + ((lane>>4)&1)*8;

    float acc[4][4][4];
#pragma unroll
    for (int i=0;i<4;i++)
#pragma unroll
        for (int j=0;j<4;j++)
#pragma unroll
            for (int t=0;t<4;t++) acc[i][j][t] = 0.f;

    const int NT = K>>6;
    // prologue: tiles 0..2
    g_load(Ag, Bg, 0, As0, Bs0, K, N, tid); cp_commit();
    if (NT > 1){ g_load(Ag, Bg, 1, As0 + ASTG, Bs0 + BSTG, K, N, tid); cp_commit(); }
    if (NT > 2){ g_load(Ag, Bg, 2, As0 + 2*ASTG, Bs0 + 2*BSTG, K, N, tid); cp_commit(); }

    int buf = 0;
    for (int kt=0; kt<NT; ++kt){
        if (kt >= NT-1) cp_wait<0>();
        else if (kt == NT-2) cp_wait<1>();
        else cp_wait<2>();
        __syncthreads();
        if (kt+3 < NT){
            int nb = buf+3; if (nb >= GSTAGES) nb -= GSTAGES;
            g_load(Ag, Bg, kt+3, As0 + nb*ASTG, Bs0 + nb*BSTG, K, N, tid);
            cp_commit();
        }

        const __half* As = As0 + buf*ASTG;
        const __half* Bs = Bs0 + buf*BSTG;
#pragma unroll
        for (int ks=0; ks<64; ks+=16){
            uint32_t afr[4][4];
#pragma unroll
            for (int mt=0; mt<4; ++mt)
                ldm_x4(afr[mt], smem_u32(As + (a_r + mt*16)*AP2 + ks + a_c));
            uint32_t bfr[2][4];
#pragma unroll
            for (int ng=0; ng<2; ++ng)
                ldm_x4t(bfr[ng], smem_u32(Bs + (ks + b_k)*BP2 + b_n + ng*16));
#pragma unroll
            for (int mt=0; mt<4; ++mt)
#pragma unroll
                for (int nt=0; nt<4; ++nt)
                    mma16816(acc[mt][nt], afr[mt], &bfr[nt>>1][(nt&1)*2]);
        }
        ++buf; if (buf >= GSTAGES) buf = 0;
    }

    // epilogue (with optional QKV routing)
    OutT* Cout = C0;
    int ldc = N;
    int cb = blockIdx.x*128;
    if (NSPLIT == 3){
        ldc = N/3;
        const int per = ldc >> 7;                 // 128-col tiles per tensor
        const int t = blockIdx.x / per;
        Cout = (t==0) ? C0 : ((t==1) ? C1 : C2);
        cb = (blockIdx.x - t*per)*128;
    }
#pragma unroll
    for (int mt=0; mt<4; ++mt){
        const int row0 = blockIdx.y*128 + wm*64 + mt*16 + gr;
#pragma unroll
        for (int nt=0; nt<4; ++nt){
            const int col = cb + wn*32 + nt*8 + tig*2;
            float v0 = acc[mt][nt][0], v1 = acc[mt][nt][1];
            float v2 = acc[mt][nt][2], v3 = acc[mt][nt][3];
            if (BIAS){
                float b0 = bias[col], b1 = bias[col+1];
                v0 += b0; v1 += b1; v2 += b0; v3 += b1;
            }
            if (RELU){
                v0 = fmaxf(v0,0.f); v1 = fmaxf(v1,0.f);
                v2 = fmaxf(v2,0.f); v3 = fmaxf(v3,0.f);
            }
            if constexpr (sizeof(OutT) == 2){
                *reinterpret_cast<uint32_t*>((__half*)Cout + (size_t)row0*ldc + col)     = packh2(v0,v1);
                *reinterpret_cast<uint32_t*>((__half*)Cout + (size_t)(row0+8)*ldc + col) = packh2(v2,v3);
            } else {
                *reinterpret_cast<float2*>((float*)Cout + (size_t)row0*ldc + col)     = make_float2(v0,v1);
                *reinterpret_cast<float2*>((float*)Cout + (size_t)(row0+8)*ldc + col) = make_float2(v2,v3);
            }
        }
    }
}

// ---------------------------------------------------------------------------
// RoPE: q and k in one launch, half2 vectorized (2 rotations per thread)
// ---------------------------------------------------------------------------
__global__ void rope_h2(__half* __restrict__ q, __half* __restrict__ k){
    int idx = blockIdx.x*blockDim.x + threadIdx.x;
    if (idx >= 2*BL*NH*16) return;
    int i2 = idx & 15;                 // covers dims 2*i2, 2*i2+1
    int h = (idx>>4) & (NH-1);
    int row = (idx>>8) & (BL-1);
    int t = idx >> 20;                 // BL*NH*16 = 2^20
    int l = row & (LL-1);

    float fl = (float)l;
    float inv0 = powf(10000.f, -(float)(4*i2)   / (float)DK);
    float inv1 = powf(10000.f, -(float)(4*i2+2) / (float)DK);
    float s0, c0, s1, c1;
    sincosf(fl*inv0, &s0, &c0);
    sincosf(fl*inv1, &s1, &c1);

    __half* base = (t ? k : q) + (size_t)row*DD + h*DK + i2*2;
    __half2 a = *(__half2*)(base);
    __half2 b = *(__half2*)(base + 32);
    float2 x1 = __half22float2(a), x2 = __half22float2(b);
    *(__half2*)(base)      = __floats2half2_rn(x1.x*c0 - x2.x*s0, x1.y*c1 - x2.y*s1);
    *(__half2*)(base + 32) = __floats2half2_rn(x1.x*s0 + x2.x*c0, x1.y*s1 + x2.y*c1);
}

// ---------------------------------------------------------------------------
// flash attention: Q tile 128 (8 warps / 256 thr), 64-key tiles, dbl-buffer
// ---------------------------------------------------------------------------
#define FP 72
#define FSMEM ((128*FP + 4*64*FP) * 2)   // 55296 bytes

__device__ __forceinline__ void flash_load_kv(const __half* __restrict__ K,
    const __half* __restrict__ V, size_t base, int kt,
    __half* ks, __half* vs, int tid)
{
#pragma unroll
    for (int c0=0;c0<2;c0++){
        int c = tid + c0*256;
        int r = c>>3, cu = (c&7)*8;
        size_t g = base + (size_t)(kt*64 + r)*DD + cu;
        cp16(smem_u32(ks + r*FP + cu), K+g);
        cp16(smem_u32(vs + r*FP + cu), V+g);
    }
}

__global__ void __launch_bounds__(256,1) flash_h(const __half* __restrict__ Q,
    const __half* __restrict__ K, const __half* __restrict__ V, __half* __restrict__ O)
{
    extern __shared__ __align__(16) __half fsm[];
    __half* Qs = fsm;
    __half* Ks = Qs + 128*FP;
    __half* Vs = Ks + 2*64*FP;

    const int qt = blockIdx.x, bh = blockIdx.y;
    const int b = bh >> 4, h = bh & 15;
    const size_t base = (size_t)b*LL*DD + (size_t)h*DK;
    const int tid = threadIdx.x, warp = tid>>5, lane = tid&31;
    const int gr = lane>>2, tig = lane&3;

    flash_load_kv(K, V, base, 0, Ks, Vs, tid);
    cp_commit();

    const float qsc = 0.125f * 1.4426950408889634f;
#pragma unroll
    for (int c0=0;c0<4;c0++){
        int c = tid + c0*256;
        int r = c>>3, cu = (c&7)*8;
        uint4 raw = *(const uint4*)(Q + base + (size_t)(qt*128 + r)*DD + cu);
        __half2* hp = (__half2*)&raw;
#pragma unroll
        for (int j=0;j<4;j++){
            float2 f = __half22float2(hp[j]);
            hp[j] = __floats2half2_rn(f.x*qsc, f.y*qsc);
        }
        *(uint4*)&Qs[r*FP + cu] = raw;
    }
    __syncthreads();

    uint32_t qa[4][4];
    {
        const int qr = warp*16 + (lane&15);
        const int qc = (lane>>4)*8;
#pragma unroll
        for (int kb=0; kb<4; ++kb)
            ldm_x4(qa[kb], smem_u32(&Qs[qr*FP + kb*16 + qc]));
    }

    float m0 = -1e30f, m1 = -1e30f, l0 = 0.f, l1 = 0.f;
    float oc[8][4];
#pragma unroll
    for (int d=0; d<8; ++d)
#pragma unroll
        for (int t=0; t<4; ++t) oc[d][t] = 0.f;

    const int k_n = (lane&7) + ((lane>>4)&1)*8;
    const int k_c = ((lane>>3)&1)*8;
    const int v_k = (lane&7) + ((lane>>3)&1)*8;
    const int v_n = ((lane>>4)&1)*8;

    for (int kt=0; kt<LL/64; ++kt){
        const int buf = kt&1;
        if (kt+1 < LL/64){
            flash_load_kv(K, V, base, kt+1, Ks + (buf^1)*64*FP, Vs + (buf^1)*64*FP, tid);
            cp_commit();
            cp_wait<1>();
        } else {
            cp_wait<0>();
        }
        __syncthreads();

        const __half* kbuf = Ks + buf*64*FP;
        const __half* vbuf = Vs + buf*64*FP;

        float s[8][4];
#pragma unroll
        for (int nt=0; nt<8; ++nt)
#pragma unroll
            for (int t=0; t<4; ++t) s[nt][t] = 0.f;
#pragma unroll
        for (int kb=0; kb<4; ++kb){
#pragma unroll
            for (int ng=0; ng<4; ++ng){
                uint32_t kf[4];
                ldm_x4(kf, smem_u32(kbuf + (ng*16 + k_n)*FP + kb*16 + k_c));
                mma16816(s[2*ng],   qa[kb], kf);
                mma16816(s[2*ng+1], qa[kb], kf+2);
            }
        }

        float mx0 = -1e30f, mx1 = -1e30f;
#pragma unroll
        for (int nt=0; nt<8; ++nt){
            mx0 = fmaxf(mx0, fmaxf(s[nt][0], s[nt][1]));
            mx1 = fmaxf(mx1, fmaxf(s[nt][2], s[nt][3]));
        }
        mx0 = fmaxf(mx0, __shfl_xor_sync(0xffffffffu, mx0, 1));
        mx0 = fmaxf(mx0, __shfl_xor_sync(0xffffffffu, mx0, 2));
        mx1 = fmaxf(mx1, __shfl_xor_sync(0xffffffffu, mx1, 1));
        mx1 = fmaxf(mx1, __shfl_xor_sync(0xffffffffu, mx1, 2));

        float mn0 = fmaxf(m0, mx0), mn1 = fmaxf(m1, mx1);
        float f0 = exp2f(m0 - mn0), f1 = exp2f(m1 - mn1);
        m0 = mn0; m1 = mn1;

        float r0 = 0.f, r1 = 0.f;
#pragma unroll
        for (int nt=0; nt<8; ++nt){
            s[nt][0] = exp2f(s[nt][0] - mn0);
            s[nt][1] = exp2f(s[nt][1] - mn0);
            s[nt][2] = exp2f(s[nt][2] - mn1);
            s[nt][3] = exp2f(s[nt][3] - mn1);
            r0 += s[nt][0] + s[nt][1];
            r1 += s[nt][2] + s[nt][3];
        }
        r0 += __shfl_xor_sync(0xffffffffu, r0, 1);
        r0 += __shfl_xor_sync(0xffffffffu, r0, 2);
        r1 += __shfl_xor_sync(0xffffffffu, r1, 1);
        r1 += __shfl_xor_sync(0xffffffffu, r1, 2);
        l0 = l0*f0 + r0; l1 = l1*f1 + r1;

#pragma unroll
        for (int d=0; d<8; ++d){
            oc[d][0] *= f0; oc[d][1] *= f0;
            oc[d][2] *= f1; oc[d][3] *= f1;
        }

        uint32_t pa[4][4];
#pragma unroll
        for (int kb=0; kb<4; ++kb){
            pa[kb][0] = packh2(s[2*kb][0],   s[2*kb][1]);
            pa[kb][1] = packh2(s[2*kb][2],   s[2*kb][3]);
            pa[kb][2] = packh2(s[2*kb+1][0], s[2*kb+1][1]);
            pa[kb][3] = packh2(s[2*kb+1][2], s[2*kb+1][3]);
        }

#pragma unroll
        for (int kb=0; kb<4; ++kb){
#pragma unroll
            for (int ng=0; ng<4; ++ng){
                uint32_t vf[4];
                ldm_x4t(vf, smem_u32(vbuf + (kb*16 + v_k)*FP + ng*16 + v_n));
                mma16816(oc[2*ng],   pa[kb], vf);
                mma16816(oc[2*ng+1], pa[kb], vf+2);
            }
        }
        __syncthreads();
    }

    const float i0 = 1.f/l0, i1 = 1.f/l1;
    const int r0g = qt*128 + warp*16 + gr;
#pragma unroll
    for (int d=0; d<8; ++d){
        const int col = d*8 + tig*2;
        *reinterpret_cast<uint32_t*>(O + base + (size_t)r0g*DD + col)     = packh2(oc[d][0]*i0, oc[d][1]*i0);
        *reinterpret_cast<uint32_t*>(O + base + (size_t)(r0g+8)*DD + col) = packh2(oc[d][2]*i1, oc[d][3]*i1);
    }
}

// ---------------------------------------------------------------------------
// out = LayerNorm(a+b); optionally also write half copy
// ---------------------------------------------------------------------------
template<bool DUAL>
__global__ void add_ln(const float* __restrict__ a, const float* __restrict__ b,
                       const float* __restrict__ gamma, const float* __restrict__ beta,
                       float* __restrict__ o, __half* __restrict__ o2)
{
    const int row = blockIdx.x;
    const int tid = threadIdx.x;
    const float* pa = a + (size_t)row*DD;
    const float* pb = b + (size_t)row*DD;

    float v[4];
    float s = 0.f;
#pragma unroll
    for (int i=0;i<4;i++){
        int c = tid + i*256;
        v[i] = pa[c] + pb[c];
        s += v[i];
    }

    __shared__ float red[8];
    __shared__ float smean, srstd;
#pragma unroll
    for (int off=16; off; off>>=1) s += __shfl_xor_sync(0xffffffffu, s, off);
    if ((tid&31)==0) red[tid>>5] = s;
    __syncthreads();
    if (tid==0){
        float t=0.f;
#pragma unroll
        for (int i=0;i<8;i++) t += red[i];
        smean = t * (1.f/(float)DD);
    }
    __syncthreads();
    float mean = smean;

    float s2 = 0.f;
#pragma unroll
    for (int i=0;i<4;i++){ float d = v[i]-mean; s2 += d*d; }
#pragma unroll
    for (int off=16; off; off>>=1) s2 += __shfl_xor_sync(0xffffffffu, s2, off);
    if ((tid&31)==0) red[tid>>5] = s2;
    __syncthreads();
    if (tid==0){
        float t=0.f;
#pragma unroll
        for (int i=0;i<8;i++) t += red[i];
        srstd = rsqrtf(t * (1.f/(float)DD) + 1e-6f);
    }
    __syncthreads();
    float rstd = srstd;

    float* po = o + (size_t)row*DD;
#pragma unroll
    for (int i=0;i<4;i++){
        int c = tid + i*256;
        float r = gamma[c]*(v[i]-mean)*rstd + beta[c];
        po[c] = r;
        if (DUAL) o2[(size_t)row*DD + c] = __float2half_rn(r);
    }
}

// ---------------------------------------------------------------------------
// Launch
// ---------------------------------------------------------------------------
extern "C" void kernel_launch(void* const* d_in, const int* in_sizes, int n_in,
                              void* d_out, int out_size) {
    const float* x      = (const float*)d_in[0];
    const float* w_q    = (const float*)d_in[1];
    const float* w_k    = (const float*)d_in[2];
    const float* w_v    = (const float*)d_in[3];
    const float* w_o    = (const float*)d_in[4];
    const float* b_o    = (const float*)d_in[5];
    const float* gamma1 = (const float*)d_in[6];
    const float* beta1  = (const float*)d_in[7];
    const float* gamma2 = (const float*)d_in[8];
    const float* beta2  = (const float*)d_in[9];
    const float* w1     = (const float*)d_in[10];
    const float* b1     = (const float*)d_in[11];
    const float* w2     = (const float*)d_in[12];
    const float* b2     = (const float*)d_in[13];
    float* out = (float*)d_out;

    __half* hbase = nullptr;  float* fbase = nullptr;
    cudaGetSymbolAddress((void**)&hbase, g_h);
    cudaGetSymbolAddress((void**)&fbase, g_f);

    const size_t M1 = (size_t)BL*DD;
    const size_t W  = (size_t)DD*DD;
    const size_t W1 = (size_t)DD*FF;
    const size_t F1 = (size_t)BL*FF;

    __half* xh   = hbase;
    __half* q    = xh  + M1;
    __half* k    = q   + M1;
    __half* v    = k   + M1;
    __half* ctx  = v   + M1;
    __half* hh   = ctx + M1;
    __half* ff1  = hh  + M1;
    __half* wqkv = ff1 + F1;        // [DD, 3*DD]
    __half* woh  = wqkv + 3*W;
    __half* w1h  = woh + W;
    __half* w2h  = w1h + W1;

    float* attnf = fbase;
    float* hbuf  = attnf + M1;
    float* ff2f  = hbuf  + M1;

    cudaFuncSetAttribute(hgemm2<__half,false,false,3>, cudaFuncAttributeMaxDynamicSharedMemorySize, GSMEM);
    cudaFuncSetAttribute(hgemm2<float, true, false,1>, cudaFuncAttributeMaxDynamicSharedMemorySize, GSMEM);
    cudaFuncSetAttribute(hgemm2<__half,true, true ,1>, cudaFuncAttributeMaxDynamicSharedMemorySize, GSMEM);
    cudaFuncSetAttribute(flash_h, cudaFuncAttributeMaxDynamicSharedMemorySize, FSMEM);

    dim3 blk256(256);
    // conversions
    f2h <<<(int)((M1/4+255)/256), blk256>>>(x, xh, (int)M1);
    f2h3<<<(int)((W /4+255)/256), blk256>>>(w_q, w_k, w_v, wqkv);
    f2h <<<(int)((W /4+255)/256), blk256>>>(w_o, woh, (int)W);
    f2h <<<(int)((W1/4+255)/256), blk256>>>(w1,  w1h, (int)W1);
    f2h <<<(int)((W1/4+255)/256), blk256>>>(w2,  w2h, (int)W1);

    // fused QKV projection: [4096, 3072]
    dim3 gqkv(3*DD/128, BL/128);
    hgemm2<__half,false,false,3><<<gqkv, blk256, GSMEM>>>(xh, wqkv, nullptr, q, k, v, BL, 3*DD, DD);

    // RoPE (q and k, one launch)
    int rope_total = 2*BL*NH*16;
    rope_h2<<<(rope_total+255)/256, blk256>>>(q, k);

    // attention
    dim3 gattn(LL/128, BB*NH);
    flash_h<<<gattn, blk256, FSMEM>>>(q, k, v, ctx);

    // output projection
    dim3 gproj(DD/128, BL/128);
    hgemm2<float,true,false,1><<<gproj, blk256, GSMEM>>>(ctx, woh, b_o, attnf, nullptr, nullptr, BL, DD, DD);

    // h = LN(x + attn)
    add_ln<true><<<BL, blk256>>>(x, attnf, gamma1, beta1, hbuf, hh);

    // FFN
    dim3 gff1(FF/128, BL/128);
    hgemm2<__half,true,true,1><<<gff1, blk256, GSMEM>>>(hh, w1h, b1, ff1, nullptr, nullptr, BL, FF, DD);
    dim3 gff2(DD/128, BL/128);
    hgemm2<float,true,false,1><<<gff2, blk256, GSMEM>>>(ff1, w2h, b2, ff2f, nullptr, nullptr, BL, DD, FF);

    // out = LN(h + ff2)
    add_ln<false><<<BL, blk256>>>(hbuf, ff2f, gamma2, beta2, out, nullptr);
}

// round 6
// speedup vs baseline: 6.4944x; 1.0335x over previous
#include <cuda_runtime.h>
#include <cuda_fp16.h>
#include <math.h>
#include <stdint.h>

#define BB 2
#define LL 2048
#define DD 1024
#define FF 4096
#define NH 16
#define DK 64
#define BL (BB*LL)

// ---------------------------------------------------------------------------
// Scratch (device globals; no allocations allowed)
// ---------------------------------------------------------------------------
__device__ __half g_h[(size_t)6*BL*DD + (size_t)BL*FF + (size_t)4*DD*DD + (size_t)2*DD*FF];
__device__ float  g_f[(size_t)3*BL*DD];

// ---------------------------------------------------------------------------
// PTX helpers
// ---------------------------------------------------------------------------
__device__ __forceinline__ uint32_t smem_u32(const void* p){
    return (uint32_t)__cvta_generic_to_shared(p);
}
__device__ __forceinline__ void cp16(uint32_t s, const void* g){
    asm volatile("cp.async.cg.shared.global [%0], [%1], 16;\n" :: "r"(s), "l"(g));
}
__device__ __forceinline__ void cp_commit(){ asm volatile("cp.async.commit_group;\n"); }
template<int N> __device__ __forceinline__ void cp_wait(){
    asm volatile("cp.async.wait_group %0;\n" :: "n"(N));
}
__device__ __forceinline__ void ldm_x4(uint32_t* r, uint32_t addr){
    asm volatile("ldmatrix.sync.aligned.m8n8.x4.shared.b16 {%0,%1,%2,%3}, [%4];\n"
        : "=r"(r[0]),"=r"(r[1]),"=r"(r[2]),"=r"(r[3]) : "r"(addr));
}
__device__ __forceinline__ void ldm_x4t(uint32_t* r, uint32_t addr){
    asm volatile("ldmatrix.sync.aligned.m8n8.x4.trans.shared.b16 {%0,%1,%2,%3}, [%4];\n"
        : "=r"(r[0]),"=r"(r[1]),"=r"(r[2]),"=r"(r[3]) : "r"(addr));
}
__device__ __forceinline__ void mma16816(float* d, const uint32_t* a, const uint32_t* b){
    asm volatile("mma.sync.aligned.m16n8k16.row.col.f32.f16.f16.f32 "
        "{%0,%1,%2,%3}, {%4,%5,%6,%7}, {%8,%9}, {%0,%1,%2,%3};\n"
        : "+f"(d[0]),"+f"(d[1]),"+f"(d[2]),"+f"(d[3])
        : "r"(a[0]),"r"(a[1]),"r"(a[2]),"r"(a[3]), "r"(b[0]),"r"(b[1]));
}
// fp16-accumulator variant (double-rate)
__device__ __forceinline__ void mma16816h(uint32_t* d, const uint32_t* a, const uint32_t* b){
    asm volatile("mma.sync.aligned.m16n8k16.row.col.f16.f16.f16.f16 "
        "{%0,%1}, {%2,%3,%4,%5}, {%6,%7}, {%0,%1};\n"
        : "+r"(d[0]),"+r"(d[1])
        : "r"(a[0]),"r"(a[1]),"r"(a[2]),"r"(a[3]), "r"(b[0]),"r"(b[1]));
}
__device__ __forceinline__ uint32_t packh2(float x, float y){
    __half2 h = __floats2half2_rn(x, y);
    return *reinterpret_cast<uint32_t*>(&h);
}

// ---------------------------------------------------------------------------
// conversions
// ---------------------------------------------------------------------------
__global__ void f2h(const float* __restrict__ s, __half* __restrict__ d, int n){
    int i = (blockIdx.x*blockDim.x + threadIdx.x)*4;
    if (i >= n) return;
    float4 f = *(const float4*)(s+i);
    __half2 lo = __floats2half2_rn(f.x, f.y);
    __half2 hi = __floats2half2_rn(f.z, f.w);
    uint2 u; u.x = *reinterpret_cast<uint32_t*>(&lo); u.y = *reinterpret_cast<uint32_t*>(&hi);
    *(uint2*)(d+i) = u;
}

__global__ void f2h3(const float* __restrict__ a, const float* __restrict__ b,
                     const float* __restrict__ c, __half* __restrict__ d){
    int i = (blockIdx.x*blockDim.x + threadIdx.x)*4;
    if (i >= DD*DD) return;
    int kk = i >> 10, n = i & (DD-1);
    const float* srcs[3] = {a, b, c};
#pragma unroll
    for (int t=0;t<3;t++){
        float4 f = *(const float4*)(srcs[t]+i);
        __half2 lo = __floats2half2_rn(f.x, f.y);
        __half2 hi = __floats2half2_rn(f.z, f.w);
        uint2 u; u.x = *reinterpret_cast<uint32_t*>(&lo); u.y = *reinterpret_cast<uint32_t*>(&hi);
        *(uint2*)(d + (size_t)kk*3*DD + t*DD + n) = u;
    }
}

// ---------------------------------------------------------------------------
// fp16 GEMM: C[M,N] = A[M,K] @ B[K,N] (+bias)(+relu)(+fp32 residual), fp32 accum
// MT x 128 x 64 tile (MT=128 or 64), 4-stage cp.async, 256 thr (8 warps 2x4)
// ---------------------------------------------------------------------------
#define AP2 72
#define BP2 136
#define BSTG (64*BP2)
#define GSTAGES 4
#define GSMEM_MT(MT) (((MT)*AP2 + BSTG) * GSTAGES * 2)

template<int MT>
__device__ __forceinline__ void g_load(const __half* __restrict__ Ag,
    const __half* __restrict__ Bg, int kt, __half* As, __half* Bs,
    int K, int N, int tid)
{
    const __half* a = Ag + (size_t)kt*64;
    const __half* b = Bg + (size_t)kt*64*N;
#pragma unroll
    for (int i=0;i<MT/32;i++){
        int c = tid + i*256;
        int r = c>>3, k16 = c&7;
        cp16(smem_u32(As + r*AP2 + k16*8), a + (size_t)r*K + k16*8);
    }
#pragma unroll
    for (int i=0;i<4;i++){
        int c = tid + i*256;
        int r = c>>4, n16 = c&15;
        cp16(smem_u32(Bs + r*BP2 + n16*8), b + (size_t)r*N + n16*8);
    }
}

template<typename OutT, int MT, bool BIAS, bool RELU, bool RESID, int NSPLIT>
__global__ void __launch_bounds__(256,1) hgemm2(const __half* __restrict__ A,
    const __half* __restrict__ Bm, const float* __restrict__ bias,
    const float* __restrict__ res,
    OutT* __restrict__ C0, OutT* __restrict__ C1, OutT* __restrict__ C2,
    int M, int N, int K)
{
    constexpr int ASTG = MT*AP2;
    constexpr int AFR  = MT/32;      // A fragments per warp (m16 each)
    constexpr int WR   = MT/2;       // rows per wm group
    extern __shared__ __align__(16) __half sm2[];
    __half* As0 = sm2;
    __half* Bs0 = sm2 + GSTAGES*ASTG;

    const int tid = threadIdx.x;
    const int warp = tid>>5, lane = tid&31;
    const int wm = warp>>2, wn = warp&3;
    const int gr = lane>>2, tig = lane&3;

    const __half* Ag = A + (size_t)(blockIdx.y*MT)*K;
    const __half* Bg = Bm + blockIdx.x*128;

    const int a_r = wm*WR + (lane&15);
    const int a_c = (lane>>4)*8;
    const int b_k = (lane&7) + ((lane>>3)&1)*8;
    const int b_n = wn*32 + ((lane>>4)&1)*8;

    float acc[AFR][4][4];
#pragma unroll
    for (int i=0;i<AFR;i++)
#pragma unroll
        for (int j=0;j<4;j++)
#pragma unroll
            for (int t=0;t<4;t++) acc[i][j][t] = 0.f;

    const int NT = K>>6;
    g_load<MT>(Ag, Bg, 0, As0, Bs0, K, N, tid); cp_commit();
    if (NT > 1){ g_load<MT>(Ag, Bg, 1, As0 + ASTG, Bs0 + BSTG, K, N, tid); cp_commit(); }
    if (NT > 2){ g_load<MT>(Ag, Bg, 2, As0 + 2*ASTG, Bs0 + 2*BSTG, K, N, tid); cp_commit(); }

    int buf = 0;
    for (int kt=0; kt<NT; ++kt){
        if (kt >= NT-1) cp_wait<0>();
        else if (kt == NT-2) cp_wait<1>();
        else cp_wait<2>();
        __syncthreads();
        if (kt+3 < NT){
            int nb = buf+3; if (nb >= GSTAGES) nb -= GSTAGES;
            g_load<MT>(Ag, Bg, kt+3, As0 + nb*ASTG, Bs0 + nb*BSTG, K, N, tid);
            cp_commit();
        }

        const __half* As = As0 + buf*ASTG;
        const __half* Bs = Bs0 + buf*BSTG;
#pragma unroll
        for (int ks=0; ks<64; ks+=16){
            uint32_t afr[AFR][4];
#pragma unroll
            for (int mt=0; mt<AFR; ++mt)
                ldm_x4(afr[mt], smem_u32(As + (a_r + mt*16)*AP2 + ks + a_c));
            uint32_t bfr[2][4];
#pragma unroll
            for (int ng=0; ng<2; ++ng)
                ldm_x4t(bfr[ng], smem_u32(Bs + (ks + b_k)*BP2 + b_n + ng*16));
#pragma unroll
            for (int mt=0; mt<AFR; ++mt)
#pragma unroll
                for (int nt=0; nt<4; ++nt)
                    mma16816(acc[mt][nt], afr[mt], &bfr[nt>>1][(nt&1)*2]);
        }
        ++buf; if (buf >= GSTAGES) buf = 0;
    }

    OutT* Cout = C0;
    int ldc = N;
    int cb = blockIdx.x*128;
    if (NSPLIT == 3){
        ldc = N/3;
        const int per = ldc >> 7;
        const int t = blockIdx.x / per;
        Cout = (t==0) ? C0 : ((t==1) ? C1 : C2);
        cb = (blockIdx.x - t*per)*128;
    }
#pragma unroll
    for (int mt=0; mt<AFR; ++mt){
        const int row0 = blockIdx.y*MT + wm*WR + mt*16 + gr;
#pragma unroll
        for (int nt=0; nt<4; ++nt){
            const int col = cb + wn*32 + nt*8 + tig*2;
            float v0 = acc[mt][nt][0], v1 = acc[mt][nt][1];
            float v2 = acc[mt][nt][2], v3 = acc[mt][nt][3];
            if (BIAS){
                float b0 = bias[col], b1 = bias[col+1];
                v0 += b0; v1 += b1; v2 += b0; v3 += b1;
            }
            if (RESID){
                float2 r0 = *(const float2*)(res + (size_t)row0*ldc + col);
                float2 r1 = *(const float2*)(res + (size_t)(row0+8)*ldc + col);
                v0 += r0.x; v1 += r0.y; v2 += r1.x; v3 += r1.y;
            }
            if (RELU){
                v0 = fmaxf(v0,0.f); v1 = fmaxf(v1,0.f);
                v2 = fmaxf(v2,0.f); v3 = fmaxf(v3,0.f);
            }
            if constexpr (sizeof(OutT) == 2){
                *reinterpret_cast<uint32_t*>((__half*)Cout + (size_t)row0*ldc + col)     = packh2(v0,v1);
                *reinterpret_cast<uint32_t*>((__half*)Cout + (size_t)(row0+8)*ldc + col) = packh2(v2,v3);
            } else {
                *reinterpret_cast<float2*>((float*)Cout + (size_t)row0*ldc + col)     = make_float2(v0,v1);
                *reinterpret_cast<float2*>((float*)Cout + (size_t)(row0+8)*ldc + col) = make_float2(v2,v3);
            }
        }
    }
}

// ---------------------------------------------------------------------------
// RoPE: q and k in one launch, half2 vectorized
// ---------------------------------------------------------------------------
__global__ void rope_h2(__half* __restrict__ q, __half* __restrict__ k){
    int idx = blockIdx.x*blockDim.x + threadIdx.x;
    if (idx >= 2*BL*NH*16) return;
    int i2 = idx & 15;
    int h = (idx>>4) & (NH-1);
    int row = (idx>>8) & (BL-1);
    int t = idx >> 20;
    int l = row & (LL-1);

    float fl = (float)l;
    float inv0 = powf(10000.f, -(float)(4*i2)   / (float)DK);
    float inv1 = powf(10000.f, -(float)(4*i2+2) / (float)DK);
    float s0, c0, s1, c1;
    sincosf(fl*inv0, &s0, &c0);
    sincosf(fl*inv1, &s1, &c1);

    __half* base = (t ? k : q) + (size_t)row*DD + h*DK + i2*2;
    __half2 a = *(__half2*)(base);
    __half2 b = *(__half2*)(base + 32);
    float2 x1 = __half22float2(a), x2 = __half22float2(b);
    *(__half2*)(base)      = __floats2half2_rn(x1.x*c0 - x2.x*s0, x1.y*c1 - x2.y*s1);
    *(__half2*)(base + 32) = __floats2half2_rn(x1.x*s0 + x2.x*c0, x1.y*s1 + x2.y*c1);
}

// ---------------------------------------------------------------------------
// flash attention: Q tile 128, 64-key tiles, dbl-buffer; S in fp16 accum
// ---------------------------------------------------------------------------
#define FP 72
#define FSMEM ((128*FP + 4*64*FP) * 2)

__device__ __forceinline__ void flash_load_kv(const __half* __restrict__ K,
    const __half* __restrict__ V, size_t base, int kt,
    __half* ks, __half* vs, int tid)
{
#pragma unroll
    for (int c0=0;c0<2;c0++){
        int c = tid + c0*256;
        int r = c>>3, cu = (c&7)*8;
        size_t g = base + (size_t)(kt*64 + r)*DD + cu;
        cp16(smem_u32(ks + r*FP + cu), K+g);
        cp16(smem_u32(vs + r*FP + cu), V+g);
    }
}

__global__ void __launch_bounds__(256,1) flash_h(const __half* __restrict__ Q,
    const __half* __restrict__ K, const __half* __restrict__ V, __half* __restrict__ O)
{
    extern __shared__ __align__(16) __half fsm[];
    __half* Qs = fsm;
    __half* Ks = Qs + 128*FP;
    __half* Vs = Ks + 2*64*FP;

    const int qt = blockIdx.x, bh = blockIdx.y;
    const int b = bh >> 4, h = bh & 15;
    const size_t base = (size_t)b*LL*DD + (size_t)h*DK;
    const int tid = threadIdx.x, warp = tid>>5, lane = tid&31;
    const int gr = lane>>2, tig = lane&3;

    flash_load_kv(K, V, base, 0, Ks, Vs, tid);
    cp_commit();

    const float qsc = 0.125f * 1.4426950408889634f;
#pragma unroll
    for (int c0=0;c0<4;c0++){
        int c = tid + c0*256;
        int r = c>>3, cu = (c&7)*8;
        uint4 raw = *(const uint4*)(Q + base + (size_t)(qt*128 + r)*DD + cu);
        __half2* hp = (__half2*)&raw;
#pragma unroll
        for (int j=0;j<4;j++){
            float2 f = __half22float2(hp[j]);
            hp[j] = __floats2half2_rn(f.x*qsc, f.y*qsc);
        }
        *(uint4*)&Qs[r*FP + cu] = raw;
    }
    __syncthreads();

    uint32_t qa[4][4];
    {
        const int qr = warp*16 + (lane&15);
        const int qc = (lane>>4)*8;
#pragma unroll
        for (int kb=0; kb<4; ++kb)
            ldm_x4(qa[kb], smem_u32(&Qs[qr*FP + kb*16 + qc]));
    }

    float m0 = -1e30f, m1 = -1e30f, l0 = 0.f, l1 = 0.f;
    float oc[8][4];
#pragma unroll
    for (int d=0; d<8; ++d)
#pragma unroll
        for (int t=0; t<4; ++t) oc[d][t] = 0.f;

    const int k_n = (lane&7) + ((lane>>4)&1)*8;
    const int k_c = ((lane>>3)&1)*8;
    const int v_k = (lane&7) + ((lane>>3)&1)*8;
    const int v_n = ((lane>>4)&1)*8;

    for (int kt=0; kt<LL/64; ++kt){
        const int buf = kt&1;
        if (kt+1 < LL/64){
            flash_load_kv(K, V, base, kt+1, Ks + (buf^1)*64*FP, Vs + (buf^1)*64*FP, tid);
            cp_commit();
            cp_wait<1>();
        } else {
            cp_wait<0>();
        }
        __syncthreads();

        const __half* kbuf = Ks + buf*64*FP;
        const __half* vbuf = Vs + buf*64*FP;

        // S = Q @ K^T in fp16 accumulators (values bounded, softmax-normalized)
        uint32_t sh[8][2];
#pragma unroll
        for (int nt=0; nt<8; ++nt){ sh[nt][0] = 0u; sh[nt][1] = 0u; }
#pragma unroll
        for (int kb=0; kb<4; ++kb){
#pragma unroll
            for (int ng=0; ng<4; ++ng){
                uint32_t kf[4];
                ldm_x4(kf, smem_u32(kbuf + (ng*16 + k_n)*FP + kb*16 + k_c));
                mma16816h(sh[2*ng],   qa[kb], kf);
                mma16816h(sh[2*ng+1], qa[kb], kf+2);
            }
        }

        float s[8][4];
#pragma unroll
        for (int nt=0; nt<8; ++nt){
            float2 p0 = __half22float2(*reinterpret_cast<__half2*>(&sh[nt][0]));
            float2 p1 = __half22float2(*reinterpret_cast<__half2*>(&sh[nt][1]));
            s[nt][0] = p0.x; s[nt][1] = p0.y; s[nt][2] = p1.x; s[nt][3] = p1.y;
        }

        float mx0 = -1e30f, mx1 = -1e30f;
#pragma unroll
        for (int nt=0; nt<8; ++nt){
            mx0 = fmaxf(mx0, fmaxf(s[nt][0], s[nt][1]));
            mx1 = fmaxf(mx1, fmaxf(s[nt][2], s[nt][3]));
        }
        mx0 = fmaxf(mx0, __shfl_xor_sync(0xffffffffu, mx0, 1));
        mx0 = fmaxf(mx0, __shfl_xor_sync(0xffffffffu, mx0, 2));
        mx1 = fmaxf(mx1, __shfl_xor_sync(0xffffffffu, mx1, 1));
        mx1 = fmaxf(mx1, __shfl_xor_sync(0xffffffffu, mx1, 2));

        float mn0 = fmaxf(m0, mx0), mn1 = fmaxf(m1, mx1);
        float f0 = exp2f(m0 - mn0), f1 = exp2f(m1 - mn1);
        m0 = mn0; m1 = mn1;

        float r0 = 0.f, r1 = 0.f;
#pragma unroll
        for (int nt=0; nt<8; ++nt){
            s[nt][0] = exp2f(s[nt][0] - mn0);
            s[nt][1] = exp2f(s[nt][1] - mn0);
            s[nt][2] = exp2f(s[nt][2] - mn1);
            s[nt][3] = exp2f(s[nt][3] - mn1);
            r0 += s[nt][0] + s[nt][1];
            r1 += s[nt][2] + s[nt][3];
        }
        r0 += __shfl_xor_sync(0xffffffffu, r0, 1);
        r0 += __shfl_xor_sync(0xffffffffu, r0, 2);
        r1 += __shfl_xor_sync(0xffffffffu, r1, 1);
        r1 += __shfl_xor_sync(0xffffffffu, r1, 2);
        l0 = l0*f0 + r0; l1 = l1*f1 + r1;

#pragma unroll
        for (int d=0; d<8; ++d){
            oc[d][0] *= f0; oc[d][1] *= f0;
            oc[d][2] *= f1; oc[d][3] *= f1;
        }

        uint32_t pa[4][4];
#pragma unroll
        for (int kb=0; kb<4; ++kb){
            pa[kb][0] = packh2(s[2*kb][0],   s[2*kb][1]);
            pa[kb][1] = packh2(s[2*kb][2],   s[2*kb][3]);
            pa[kb][2] = packh2(s[2*kb+1][0], s[2*kb+1][1]);
            pa[kb][3] = packh2(s[2*kb+1][2], s[2*kb+1][3]);
        }

#pragma unroll
        for (int kb=0; kb<4; ++kb){
#pragma unroll
            for (int ng=0; ng<4; ++ng){
                uint32_t vf[4];
                ldm_x4t(vf, smem_u32(vbuf + (kb*16 + v_k)*FP + ng*16 + v_n));
                mma16816(oc[2*ng],   pa[kb], vf);
                mma16816(oc[2*ng+1], pa[kb], vf+2);
            }
        }
        __syncthreads();
    }

    const float i0 = 1.f/l0, i1 = 1.f/l1;
    const int r0g = qt*128 + warp*16 + gr;
#pragma unroll
    for (int d=0; d<8; ++d){
        const int col = d*8 + tig*2;
        *reinterpret_cast<uint32_t*>(O + base + (size_t)r0g*DD + col)     = packh2(oc[d][0]*i0, oc[d][1]*i0);
        *reinterpret_cast<uint32_t*>(O + base + (size_t)(r0g+8)*DD + col) = packh2(oc[d][2]*i1, oc[d][3]*i1);
    }
}

// ---------------------------------------------------------------------------
// out = LayerNorm(src); optionally also write half copy
// ---------------------------------------------------------------------------
template<bool DUAL>
__global__ void ln_only(const float* __restrict__ src,
                        const float* __restrict__ gamma, const float* __restrict__ beta,
                        float* __restrict__ o, __half* __restrict__ o2)
{
    const int row = blockIdx.x;
    const int tid = threadIdx.x;
    const float* ps = src + (size_t)row*DD;

    float v[4];
    float s = 0.f;
#pragma unroll
    for (int i=0;i<4;i++){
        int c = tid + i*256;
        v[i] = ps[c];
        s += v[i];
    }

    __shared__ float red[8];
    __shared__ float smean, srstd;
#pragma unroll
    for (int off=16; off; off>>=1) s += __shfl_xor_sync(0xffffffffu, s, off);
    if ((tid&31)==0) red[tid>>5] = s;
    __syncthreads();
    if (tid==0){
        float t=0.f;
#pragma unroll
        for (int i=0;i<8;i++) t += red[i];
        smean = t * (1.f/(float)DD);
    }
    __syncthreads();
    float mean = smean;

    float s2 = 0.f;
#pragma unroll
    for (int i=0;i<4;i++){ float d = v[i]-mean; s2 += d*d; }
#pragma unroll
    for (int off=16; off; off>>=1) s2 += __shfl_xor_sync(0xffffffffu, s2, off);
    if ((tid&31)==0) red[tid>>5] = s2;
    __syncthreads();
    if (tid==0){
        float t=0.f;
#pragma unroll
        for (int i=0;i<8;i++) t += red[i];
        srstd = rsqrtf(t * (1.f/(float)DD) + 1e-6f);
    }
    __syncthreads();
    float rstd = srstd;

    float* po = o + (size_t)row*DD;
#pragma unroll
    for (int i=0;i<4;i++){
        int c = tid + i*256;
        float r = gamma[c]*(v[i]-mean)*rstd + beta[c];
        po[c] = r;
        if (DUAL) o2[(size_t)row*DD + c] = __float2half_rn(r);
    }
}

// ---------------------------------------------------------------------------
// Launch
// ---------------------------------------------------------------------------
extern "C" void kernel_launch(void* const* d_in, const int* in_sizes, int n_in,
                              void* d_out, int out_size) {
    const float* x      = (const float*)d_in[0];
    const float* w_q    = (const float*)d_in[1];
    const float* w_k    = (const float*)d_in[2];
    const float* w_v    = (const float*)d_in[3];
    const float* w_o    = (const float*)d_in[4];
    const float* b_o    = (const float*)d_in[5];
    const float* gamma1 = (const float*)d_in[6];
    const float* beta1  = (const float*)d_in[7];
    const float* gamma2 = (const float*)d_in[8];
    const float* beta2  = (const float*)d_in[9];
    const float* w1     = (const float*)d_in[10];
    const float* b1     = (const float*)d_in[11];
    const float* w2     = (const float*)d_in[12];
    const float* b2     = (const float*)d_in[13];
    float* out = (float*)d_out;

    __half* hbase = nullptr;  float* fbase = nullptr;
    cudaGetSymbolAddress((void**)&hbase, g_h);
    cudaGetSymbolAddress((void**)&fbase, g_f);

    const size_t M1 = (size_t)BL*DD;
    const size_t W  = (size_t)DD*DD;
    const size_t W1 = (size_t)DD*FF;
    const size_t F1 = (size_t)BL*FF;

    __half* xh   = hbase;
    __half* q    = xh  + M1;
    __half* k    = q   + M1;
    __half* v    = k   + M1;
    __half* ctx  = v   + M1;
    __half* hh   = ctx + M1;
    __half* ff1  = hh  + M1;
    __half* wqkv = ff1 + F1;
    __half* woh  = wqkv + 3*W;
    __half* w1h  = woh + W;
    __half* w2h  = w1h + W1;

    float* sum1  = fbase;          // x + attn_out (fp32)
    float* hbuf  = sum1 + M1;      // h = LN(sum1)
    float* sum2  = hbuf + M1;      // h + ff2 (fp32)

    cudaFuncSetAttribute(hgemm2<__half,128,false,false,false,3>, cudaFuncAttributeMaxDynamicSharedMemorySize, GSMEM_MT(128));
    cudaFuncSetAttribute(hgemm2<__half,128,true, true ,false,1>, cudaFuncAttributeMaxDynamicSharedMemorySize, GSMEM_MT(128));
    cudaFuncSetAttribute(hgemm2<float, 64, true, false,true ,1>, cudaFuncAttributeMaxDynamicSharedMemorySize, GSMEM_MT(64));
    cudaFuncSetAttribute(flash_h, cudaFuncAttributeMaxDynamicSharedMemorySize, FSMEM);

    dim3 blk256(256);

    // launches ordered so the QKV GEMM is launch #5 (ncu captures it)
    f2h <<<(int)((M1/4+255)/256), blk256>>>(x, xh, (int)M1);                 // 1
    f2h3<<<(int)((W /4+255)/256), blk256>>>(w_q, w_k, w_v, wqkv);            // 2
    f2h <<<(int)((W /4+255)/256), blk256>>>(w_o, woh, (int)W);               // 3
    f2h <<<(int)((W1/4+255)/256), blk256>>>(w1,  w1h, (int)W1);              // 4

    dim3 gqkv(3*DD/128, BL/128);
    hgemm2<__half,128,false,false,false,3><<<gqkv, blk256, GSMEM_MT(128)>>>( // 5
        xh, wqkv, nullptr, nullptr, q, k, v, BL, 3*DD, DD);

    f2h <<<(int)((W1/4+255)/256), blk256>>>(w2,  w2h, (int)W1);              // 6

    int rope_total = 2*BL*NH*16;
    rope_h2<<<(rope_total+255)/256, blk256>>>(q, k);                         // 7

    dim3 gattn(LL/128, BB*NH);
    flash_h<<<gattn, blk256, FSMEM>>>(q, k, v, ctx);                         // 8

    // WO projection with fused residual: sum1 = ctx@wo + b_o + x
    dim3 gwo(DD/128, BL/64);
    hgemm2<float,64,true,false,true,1><<<gwo, blk256, GSMEM_MT(64)>>>(       // 9
        ctx, woh, b_o, x, sum1, nullptr, nullptr, BL, DD, DD);

    ln_only<true><<<BL, blk256>>>(sum1, gamma1, beta1, hbuf, hh);            // 10

    dim3 gff1(FF/128, BL/128);
    hgemm2<__half,128,true,true,false,1><<<gff1, blk256, GSMEM_MT(128)>>>(   // 11
        hh, w1h, b1, nullptr, ff1, nullptr, nullptr, BL, FF, DD);

    // FF2 with fused residual: sum2 = ff1@w2 + b2 + h
    dim3 gff2(DD/128, BL/64);
    hgemm2<float,64,true,false,true,1><<<gff2, blk256, GSMEM_MT(64)>>>(      // 12
        ff1, w2h, b2, hbuf, sum2, nullptr, nullptr, BL, DD, FF);

    ln_only<false><<<BL, blk256>>>(sum2, gamma2, beta2, out, nullptr);       // 13
}